// round 11
// baseline (speedup 1.0000x reference)
#include <cuda_runtime.h>
#include <math.h>

#define H 512
#define W 512
#define HW (512*512)
#define NB 8          // batch
#define NIMG 16       // 8 pred + 8 true
#define NUM_ITER 40
#define NFUSED (NUM_ITER/2)   // 20 fused double-steps
#define BH 16
#define NBANDS (H/BH)   // 32
#define BIGF 3.0e38f

// ---- scratch (device globals; no allocation) ----
// g_skel stores q = 1 - skel  (multiplicative form: q *= (1 - delta))
__device__ float g_imgA[(size_t)NIMG*HW];
__device__ float g_imgB[(size_t)NIMG*HW];
__device__ float g_skel[(size_t)NIMG*HW];
__device__ float g_dicePart[256*3];           // [block][inter,sumT,sumP]
__device__ float g_epPart[NIMG*NBANDS*3];     // [img][band][s,sy,sx]

__device__ __forceinline__ float f3min(float a,float b,float c){return fminf(fminf(a,b),c);}
__device__ __forceinline__ float f3max(float a,float b,float c){return fmaxf(fmaxf(a,b),c);}

// ---------------------------------------------------------------------------
// prep: prob = softmax(net)[:,1] = sigmoid(x1-x0); true->float; dice partials.
// ---------------------------------------------------------------------------
__global__ void prep_kernel(const float* __restrict__ net, const int* __restrict__ yt) {
    int tid = blockIdx.x * 256 + threadIdx.x;
    float inter = 0.f, st = 0.f, sp = 0.f;
    for (int idx = tid; idx < NB*HW; idx += 256*256) {
        int b = idx / HW;
        int p = idx - b*HW;
        float x0 = net[(size_t)b*2*HW + p];
        float x1 = net[(size_t)b*2*HW + HW + p];
        float prob = 1.f / (1.f + __expf(x0 - x1));
        float t = (float)yt[idx];
        g_imgA[(size_t)b*HW + p] = prob;
        g_imgA[(size_t)(NB + b)*HW + p] = t;
        inter += t * prob;
        st += t;
        sp += prob;
    }
    __shared__ float s[3][256];
    s[0][threadIdx.x] = inter; s[1][threadIdx.x] = st; s[2][threadIdx.x] = sp;
    __syncthreads();
    for (int off = 128; off > 0; off >>= 1) {
        if (threadIdx.x < off) {
            s[0][threadIdx.x] += s[0][threadIdx.x + off];
            s[1][threadIdx.x] += s[1][threadIdx.x + off];
            s[2][threadIdx.x] += s[2][threadIdx.x + off];
        }
        __syncthreads();
    }
    if (threadIdx.x == 0) {
        g_dicePart[blockIdx.x*3 + 0] = s[0][0];
        g_dicePart[blockIdx.x*3 + 1] = s[1][0];
        g_dicePart[blockIdx.x*3 + 2] = s[2][0];
    }
}

// ---------------------------------------------------------------------------
// INIT sweep: q = 1 - relu(img - dilate3x3(erode(img))).  (single launch)
// ---------------------------------------------------------------------------
__global__ __launch_bounds__(128) void sweep_init_kernel() {
    const int img = blockIdx.y;
    const int R0row = blockIdx.x * BH;
    const int lane = threadIdx.x & 31;
    const int colBase = ((threadIdx.x >> 5) << 7) + (lane << 2);
    const bool isL = (lane == 0), isR = (lane == 31);
    const bool edgeL = (colBase == 0), edgeR = (colBase == W-4);
    const float* __restrict__ in = g_imgA + (size_t)img*HW;
    float* __restrict__ skel = g_skel + (size_t)img*HW;

    const float4 PINF = make_float4(BIGF,BIGF,BIGF,BIGF);
    float4 i0=PINF, i1=PINF, L0=PINF, L1=PINF, Rv0=PINF, Rv1=PINF;
    float4 hp=PINF; float hpL1=BIGF, hpR0=BIGF;
    float4 e1a=make_float4(-BIGF,-BIGF,-BIGF,-BIGF), e1b=e1a;
    float e1aL=-BIGF, e1bL=-BIGF, e1aR=-BIGF, e1bR=-BIGF;

    const int rStart = R0row-2, rEnd = R0row+BH+1;   // BH+4 = 20 rows
    float4 nCur=PINF, nL=PINF, nR=PINF;
    if (rStart >= 0 && rStart < H) {
        const float* p = in + rStart*W + colBase;
        nCur = *(const float4*)p;
        if (isL && !edgeL) nL = *(const float4*)(p - 4);
        if (isR && !edgeR) nR = *(const float4*)(p + 4);
    }

    #pragma unroll 2
    for (int t = 0; t < BH+4; t++) {
        const int r = rStart + t;
        float4 cur = nCur, Lc = nL, Rc = nR;
        nCur = PINF; nL = PINF; nR = PINF;
        {
            int rn = r + 1;
            if (rn <= rEnd && (unsigned)rn < (unsigned)H) {
                const float* p = in + rn*W + colBase;
                nCur = *(const float4*)p;
                if (isL && !edgeL) nL = *(const float4*)(p - 4);
                if (isR && !edgeR) nR = *(const float4*)(p + 4);
            }
        }
        float xm1 = __shfl_up_sync(0xffffffffu, cur.w, 1); if (isL) xm1 = Lc.w;
        float xp1 = __shfl_down_sync(0xffffffffu, cur.x, 1); if (isR) xp1 = Rc.x;
        float4 hc;
        hc.x = f3min(xm1, cur.x, cur.y);
        hc.y = f3min(cur.x, cur.y, cur.z);
        hc.z = f3min(cur.y, cur.z, cur.w);
        hc.w = f3min(cur.z, cur.w, xp1);
        float hcL1 = f3min(Lc.z, Lc.w, cur.x);
        float hcR0 = f3min(cur.w, Rc.x, Rc.y);

        float4 e1n;
        e1n.x = fminf(f3min(i0.x,i1.x,cur.x), hp.x);
        e1n.y = fminf(f3min(i0.y,i1.y,cur.y), hp.y);
        e1n.z = fminf(f3min(i0.z,i1.z,cur.z), hp.z);
        e1n.w = fminf(f3min(i0.w,i1.w,cur.w), hp.w);
        float e1nL = fminf(f3min(L0.w,L1.w,Lc.w), hpL1);
        float e1nR = fminf(f3min(Rv0.x,Rv1.x,Rc.x), hpR0);
        {
            int k = r-1;
            if (k < 0 || k >= H) {
                e1n = make_float4(-BIGF,-BIGF,-BIGF,-BIGF);
                e1nL = e1nR = -BIGF;
            }
        }
        if (edgeL) e1nL = -BIGF;
        if (edgeR) e1nR = -BIGF;

        if (t >= 4) {   // r >= R0row+2
            float4 mv;
            mv.x = f3max(e1a.x, e1b.x, e1n.x);
            mv.y = f3max(e1a.y, e1b.y, e1n.y);
            mv.z = f3max(e1a.z, e1b.z, e1n.z);
            mv.w = f3max(e1a.w, e1b.w, e1n.w);
            float mvL = f3max(e1aL, e1bL, e1nL);
            float mvR = f3max(e1aR, e1bR, e1nR);
            float mm1 = __shfl_up_sync(0xffffffffu, mv.w, 1); if (isL) mm1 = mvL;
            float mp1 = __shfl_down_sync(0xffffffffu, mv.x, 1); if (isR) mp1 = mvR;
            float4 open;
            open.x = f3max(mm1, mv.x, mv.y);
            open.y = f3max(mv.x, mv.y, mv.z);
            open.z = f3max(mv.y, mv.z, mv.w);
            open.w = f3max(mv.z, mv.w, mp1);
            int k2 = r-2;
            float4 s;
            s.x = 1.f - fmaxf(i0.x - open.x, 0.f);
            s.y = 1.f - fmaxf(i0.y - open.y, 0.f);
            s.z = 1.f - fmaxf(i0.z - open.z, 0.f);
            s.w = 1.f - fmaxf(i0.w - open.w, 0.f);
            *(float4*)(skel + k2*W + colBase) = s;
        }
        i0=i1; i1=cur; L0=L1; L1=Lc; Rv0=Rv1; Rv1=Rc;
        hp=hc; hpL1=hcL1; hpR0=hcR0;
        e1a=e1b; e1b=e1n; e1aL=e1bL; e1bL=e1nL; e1aR=e1bR; e1bR=e1nR;
    }
}

// ---------------------------------------------------------------------------
// FUSED double-step body (two soft-skel iterations per launch).
//   img -> E1 -> E2 -> E3;  output image = E2
//   delta1 = relu(E1 - dilate3(E2));  delta2 = relu(E2 - dilate3(E3))
//   q *= (1-delta1)*(1-delta2)
// Pipeline: load img[r] -> E1[r-1] -> E2[r-2] -> E3[r-3] -> out[r-4].
// R11 changes vs R10: skel (q) row PREFETCHED one iteration ahead;
// L/R img histories stored as 3 scalars each (only cols -3..-1 / +4..+6 live).
// ---------------------------------------------------------------------------
template<bool BOUNDARY>
__device__ __forceinline__ void step2_body(
    const float* __restrict__ in, float* __restrict__ outImg,
    float* __restrict__ skel, int R0row, int colBase,
    bool isL, bool isR, bool edgeL, bool edgeR)
{
    const float4 PINF = make_float4(BIGF,BIGF,BIGF,BIGF);
    const float4 NINF = make_float4(-BIGF,-BIGF,-BIGF,-BIGF);

    float4 i0=PINF, i1=PINF;
    float L0y=BIGF,L0z=BIGF,L0w=BIGF, L1y=BIGF,L1z=BIGF,L1w=BIGF;
    float R0x=BIGF,R0y=BIGF,R0z=BIGF, R1x=BIGF,R1y=BIGF,R1z=BIGF;
    float4 hp=PINF; float hpL3=BIGF,hpL2=BIGF,hpL1=BIGF,hpR0=BIGF,hpR1=BIGF,hpR2=BIGF;
    float4 e1b=PINF, e1a=PINF, e1z=PINF;
    float e1bL2=BIGF,e1bL1=BIGF,e1bR0=BIGF,e1bR1=BIGF;
    float e1aL2=BIGF,e1aL1=BIGF,e1aR0=BIGF,e1aR1=BIGF;
    float4 h1p=PINF; float h1pL2=BIGF,h1pL1=BIGF,h1pR0=BIGF,h1pR1=BIGF;
    float4 e2b=PINF, e2a=PINF, e2c=PINF;
    float e2bL1=BIGF,e2bR0=BIGF,e2aL1=BIGF,e2aR0=BIGF,e2cL1=BIGF,e2cR0=BIGF;
    float4 h2p=PINF; float h2pL1=BIGF,h2pR0=BIGF;
    float4 e3b=NINF, e3a=NINF;
    float e3bL1=-BIGF,e3bR0=-BIGF,e3aL1=-BIGF,e3aR0=-BIGF;

    const int rStart = R0row-4;   // rows r = rStart .. rStart+BH+7
    // 1-row img prefetch + 1-row q prefetch
    float4 pC=PINF, pL=PINF, pR=PINF, pQ=make_float4(0,0,0,0);
    if (!BOUNDARY || ((unsigned)rStart < (unsigned)H)) {
        const float* p = in + rStart*W + colBase;
        pC = *(const float4*)p;
        if (isL && !edgeL) pL = *(const float4*)(p - 4);
        if (isR && !edgeR) pR = *(const float4*)(p + 4);
    }

    #pragma unroll 2
    for (int t = 0; t < BH+8; t++) {
        const int r = rStart + t;
        float4 cur = pC, Lc = pL, Rc = pR, qv = pQ;
        // prefetch row r+1 (img) and q row (r+1)-4
        {
            int rn = r + 1;
            if (BOUNDARY) {
                pC = PINF; pL = PINF; pR = PINF;
                if ((unsigned)rn < (unsigned)H && rn <= rStart+BH+8) {
                    const float* p = in + rn*W + colBase;
                    pC = *(const float4*)p;
                    if (isL && !edgeL) pL = *(const float4*)(p - 4);
                    if (isR && !edgeR) pR = *(const float4*)(p + 4);
                }
            } else {
                const float* p = in + rn*W + colBase;
                pC = *(const float4*)p;
                pL = PINF; pR = PINF;
                if (isL && !edgeL) pL = *(const float4*)(p - 4);
                if (isR && !edgeR) pR = *(const float4*)(p + 4);
            }
            // q rows: rn-4 in [R0row, R0row+BH-1] <=> t in [7, BH+6]; always in [0,H)
            if (t >= 7 && t <= BH+6)
                pQ = *(const float4*)(skel + (rn-4)*W + colBase);
        }

        // --- stage A: hc = hmin3(img[r]), cols -3..+6 ---
        float xm1 = __shfl_up_sync(0xffffffffu, cur.w, 1); if (isL) xm1 = Lc.w;
        float xp1 = __shfl_down_sync(0xffffffffu, cur.x, 1); if (isR) xp1 = Rc.x;
        float4 hc;
        hc.x = f3min(xm1, cur.x, cur.y);
        hc.y = f3min(cur.x, cur.y, cur.z);
        hc.z = f3min(cur.y, cur.z, cur.w);
        hc.w = f3min(cur.z, cur.w, xp1);
        float hcL3 = f3min(Lc.x, Lc.y, Lc.z);
        float hcL2 = f3min(Lc.y, Lc.z, Lc.w);
        float hcL1 = f3min(Lc.z, Lc.w, cur.x);
        float hcR0 = f3min(cur.w, Rc.x, Rc.y);
        float hcR1 = f3min(Rc.x, Rc.y, Rc.z);
        float hcR2 = f3min(Rc.y, Rc.z, Rc.w);

        // --- stage B: E1[r-1] = min(vmin3(img), hmin3(img)), cols -3..+6 ---
        float4 e1n;
        e1n.x = fminf(f3min(i0.x,i1.x,cur.x), hp.x);
        e1n.y = fminf(f3min(i0.y,i1.y,cur.y), hp.y);
        e1n.z = fminf(f3min(i0.z,i1.z,cur.z), hp.z);
        e1n.w = fminf(f3min(i0.w,i1.w,cur.w), hp.w);
        float e1nL3 = fminf(f3min(L0y,L1y,Lc.y), hpL3);
        float e1nL2 = fminf(f3min(L0z,L1z,Lc.z), hpL2);
        float e1nL1 = fminf(f3min(L0w,L1w,Lc.w), hpL1);
        float e1nR0 = fminf(f3min(R0x,R1x,Rc.x), hpR0);
        float e1nR1 = fminf(f3min(R0y,R1y,Rc.y), hpR1);
        float e1nR2 = fminf(f3min(R0z,R1z,Rc.z), hpR2);
        if (BOUNDARY) {
            int k = r-1;
            if (k < 0 || k >= H) {
                e1n = PINF;
                e1nL3=e1nL2=e1nL1=e1nR0=e1nR1=e1nR2=BIGF;
            }
        }

        // --- stage C: h1c = hmin3(E1[r-1]), cols -2..+5 ---
        float em1 = __shfl_up_sync(0xffffffffu, e1n.w, 1); if (isL) em1 = e1nL1;
        float ep1 = __shfl_down_sync(0xffffffffu, e1n.x, 1); if (isR) ep1 = e1nR0;
        float4 h1c;
        h1c.x = f3min(em1, e1n.x, e1n.y);
        h1c.y = f3min(e1n.x, e1n.y, e1n.z);
        h1c.z = f3min(e1n.y, e1n.z, e1n.w);
        h1c.w = f3min(e1n.z, e1n.w, ep1);
        float h1cL2 = f3min(e1nL3, e1nL2, e1nL1);
        float h1cL1 = f3min(e1nL2, e1nL1, e1n.x);
        float h1cR0 = f3min(e1n.w, e1nR0, e1nR1);
        float h1cR1 = f3min(e1nR0, e1nR1, e1nR2);

        // --- stage D: E2[r-2] = min(vmin3(E1), h1p), cols -2..+5 (e-flavor) ---
        float4 e2n;
        e2n.x = fminf(f3min(e1a.x,e1b.x,e1n.x), h1p.x);
        e2n.y = fminf(f3min(e1a.y,e1b.y,e1n.y), h1p.y);
        e2n.z = fminf(f3min(e1a.z,e1b.z,e1n.z), h1p.z);
        e2n.w = fminf(f3min(e1a.w,e1b.w,e1n.w), h1p.w);
        float e2nL2 = fminf(f3min(e1aL2,e1bL2,e1nL2), h1pL2);
        float e2nL1 = fminf(f3min(e1aL1,e1bL1,e1nL1), h1pL1);
        float e2nR0 = fminf(f3min(e1aR0,e1bR0,e1nR0), h1pR0);
        float e2nR1 = fminf(f3min(e1aR1,e1bR1,e1nR1), h1pR1);
        if (BOUNDARY) {
            int j = r-2;
            if (j < 0 || j >= H) {
                e2n = PINF;
                e2nL2=e2nL1=e2nR0=e2nR1=BIGF;
            }
        }

        // --- stage E: h2c = hmin3(E2[r-2]), cols -1..+4 ---
        float em2 = __shfl_up_sync(0xffffffffu, e2n.w, 1); if (isL) em2 = e2nL1;
        float ep2 = __shfl_down_sync(0xffffffffu, e2n.x, 1); if (isR) ep2 = e2nR0;
        float4 h2c;
        h2c.x = f3min(em2, e2n.x, e2n.y);
        h2c.y = f3min(e2n.x, e2n.y, e2n.z);
        h2c.z = f3min(e2n.y, e2n.z, e2n.w);
        h2c.w = f3min(e2n.z, e2n.w, ep2);
        float h2cL1 = f3min(e2nL2, e2nL1, e2n.x);
        float h2cR0 = f3min(e2n.w, e2nR0, e2nR1);

        // --- stage F: E3[r-3] = min(vmin3(E2), h2p), cols -1..+4 (dilate input) ---
        float4 e3n;
        e3n.x = fminf(f3min(e2a.x,e2b.x,e2n.x), h2p.x);
        e3n.y = fminf(f3min(e2a.y,e2b.y,e2n.y), h2p.y);
        e3n.z = fminf(f3min(e2a.z,e2b.z,e2n.z), h2p.z);
        e3n.w = fminf(f3min(e2a.w,e2b.w,e2n.w), h2p.w);
        float e3nL1 = edgeL ? -BIGF : fminf(f3min(e2aL1,e2bL1,e2nL1), h2pL1);
        float e3nR0 = edgeR ? -BIGF : fminf(f3min(e2aR0,e2bR0,e2nR0), h2pR0);
        if (BOUNDARY) {
            int m = r-3;
            if (m < 0 || m >= H) {
                e3n = NINF;
                e3nL1 = e3nR0 = -BIGF;
            }
        }

        // --- stage G: output row r-4 ---
        if (t >= 8) {
            const int k2 = r-4;
            float4 q = qv;   // prefetched
            // open1 = dilate3(E2) at row r-4 (rows r-5,r-4,r-3 = e2c,e2a,e2b)
            float4 vm;
            vm.x = f3max(e2c.x, e2a.x, e2b.x);
            vm.y = f3max(e2c.y, e2a.y, e2b.y);
            vm.z = f3max(e2c.z, e2a.z, e2b.z);
            vm.w = f3max(e2c.w, e2a.w, e2b.w);
            float vmL = edgeL ? -BIGF : f3max(e2cL1, e2aL1, e2bL1);
            float vmR = edgeR ? -BIGF : f3max(e2cR0, e2aR0, e2bR0);
            float mm1 = __shfl_up_sync(0xffffffffu, vm.w, 1); if (isL) mm1 = vmL;
            float mp1 = __shfl_down_sync(0xffffffffu, vm.x, 1); if (isR) mp1 = vmR;
            float4 o1;
            o1.x = f3max(mm1, vm.x, vm.y);
            o1.y = f3max(vm.x, vm.y, vm.z);
            o1.z = f3max(vm.y, vm.z, vm.w);
            o1.w = f3max(vm.z, vm.w, mp1);
            // open2 = dilate3(E3) at row r-4 (rows r-5,r-4,r-3 = e3a,e3b,e3n)
            float4 wm;
            wm.x = f3max(e3a.x, e3b.x, e3n.x);
            wm.y = f3max(e3a.y, e3b.y, e3n.y);
            wm.z = f3max(e3a.z, e3b.z, e3n.z);
            wm.w = f3max(e3a.w, e3b.w, e3n.w);
            float wmL = f3max(e3aL1, e3bL1, e3nL1);   // edge already -INF
            float wmR = f3max(e3aR0, e3bR0, e3nR0);
            float mm2 = __shfl_up_sync(0xffffffffu, wm.w, 1); if (isL) mm2 = wmL;
            float mp2 = __shfl_down_sync(0xffffffffu, wm.x, 1); if (isR) mp2 = wmR;
            float4 o2;
            o2.x = f3max(mm2, wm.x, wm.y);
            o2.y = f3max(wm.x, wm.y, wm.z);
            o2.z = f3max(wm.y, wm.z, wm.w);
            o2.w = f3max(wm.z, wm.w, mp2);
            // q *= (1-d1)*(1-d2);  d1 = relu(E1[r-4]-o1), d2 = relu(E2[r-4]-o2)
            float d;
            d = fmaxf(e1z.x - o1.x, 0.f); q.x -= q.x*d;
            d = fmaxf(e1z.y - o1.y, 0.f); q.y -= q.y*d;
            d = fmaxf(e1z.z - o1.z, 0.f); q.z -= q.z*d;
            d = fmaxf(e1z.w - o1.w, 0.f); q.w -= q.w*d;
            d = fmaxf(e2a.x - o2.x, 0.f); q.x -= q.x*d;
            d = fmaxf(e2a.y - o2.y, 0.f); q.y -= q.y*d;
            d = fmaxf(e2a.z - o2.z, 0.f); q.z -= q.z*d;
            d = fmaxf(e2a.w - o2.w, 0.f); q.w -= q.w*d;
            *(float4*)(skel + k2*W + colBase) = q;
            *(float4*)(outImg + k2*W + colBase) = e2a;   // new image = E2
        }

        // --- rotation ---
        i0=i1; i1=cur;
        L0y=L1y; L0z=L1z; L0w=L1w; L1y=Lc.y; L1z=Lc.z; L1w=Lc.w;
        R0x=R1x; R0y=R1y; R0z=R1z; R1x=Rc.x; R1y=Rc.y; R1z=Rc.z;
        hp=hc; hpL3=hcL3; hpL2=hcL2; hpL1=hcL1; hpR0=hcR0; hpR1=hcR1; hpR2=hcR2;
        e1z=e1a;
        e1a=e1b; e1aL2=e1bL2; e1aL1=e1bL1; e1aR0=e1bR0; e1aR1=e1bR1;
        e1b=e1n; e1bL2=e1nL2; e1bL1=e1nL1; e1bR0=e1nR0; e1bR1=e1nR1;
        h1p=h1c; h1pL2=h1cL2; h1pL1=h1cL1; h1pR0=h1cR0; h1pR1=h1cR1;
        e2c=e2a; e2cL1=e2aL1; e2cR0=e2aR0;
        e2a=e2b; e2aL1=e2bL1; e2aR0=e2bR0;
        e2b=e2n; e2bL1=e2nL1; e2bR0=e2nR0;
        h2p=h2c; h2pL1=h2cL1; h2pR0=h2cR0;
        e3a=e3b; e3aL1=e3bL1; e3aR0=e3bR0;
        e3b=e3n; e3bL1=e3nL1; e3bR0=e3nR0;
        if (BOUNDARY) {
            // flip E2 rows to dilate-flavor once erode-uses are done.
            if (r-2 >= H) { e2b = NINF; e2bL1 = e2bR0 = -BIGF; }   // bottom
            if (r-4 < 0 || r-4 >= H) { e2c = NINF; e2cL1 = e2cR0 = -BIGF; }
        }
    }
}

__global__ __launch_bounds__(128, 4) void sweep_step2_kernel(int bufsel) {
    const int img = blockIdx.y;
    const int band = blockIdx.x;
    const int R0row = band * BH;
    const int lane = threadIdx.x & 31;
    const int colBase = ((threadIdx.x >> 5) << 7) + (lane << 2);
    const bool isL = (lane == 0), isR = (lane == 31);
    const bool edgeL = (colBase == 0), edgeR = (colBase == W-4);
    const float* __restrict__ in     = (bufsel ? g_imgB : g_imgA) + (size_t)img*HW;
    float*       __restrict__ outImg = (bufsel ? g_imgA : g_imgB) + (size_t)img*HW;
    float*       __restrict__ skel   = g_skel + (size_t)img*HW;

    if (band == 0 || band == NBANDS-1)
        step2_body<true >(in, outImg, skel, R0row, colBase, isL, isR, edgeL, edgeR);
    else
        step2_body<false>(in, outImg, skel, R0row, colBase, isL, isR, edgeL, edgeR);
}

// ---------------------------------------------------------------------------
// endpoints: skel = 1 - q on load; ns = sum3x3(skel) + 9*center (zero pad);
// ep = exp(-(ns-11)^2)*center; partial sums per (img, band).
// ---------------------------------------------------------------------------
__global__ __launch_bounds__(128) void endpoint_kernel() {
    const int img = blockIdx.y;
    const int R0row = blockIdx.x * BH;
    const int lane = threadIdx.x & 31;
    const int colBase = ((threadIdx.x >> 5) << 7) + (lane << 2);
    const bool isL = (lane == 0), isR = (lane == 31);
    const bool edgeL = (colBase == 0), edgeR = (colBase == W-4);
    const float* __restrict__ sk = g_skel + (size_t)img*HW;

    const float4 Z = make_float4(0.f,0.f,0.f,0.f);
    float4 i0=Z, i1=Z; float L0w=0.f,L1w=0.f,R0x=0.f,R1x=0.f;
    float s0=0.f, sy=0.f, sx=0.f;

    const int rStart = R0row-1, rEnd = R0row+BH;    // BH+2 = 18 rows
    float4 nCur=Z; float nLw=0.f, nRx=0.f;
    if (rStart >= 0 && rStart < H) {
        const float* p = sk + rStart*W + colBase;
        float4 q = *(const float4*)p;
        nCur = make_float4(1.f-q.x, 1.f-q.y, 1.f-q.z, 1.f-q.w);
        if (isL && !edgeL) nLw = 1.f - p[-1];
        if (isR && !edgeR) nRx = 1.f - p[4];
    }

    #pragma unroll 2
    for (int t = 0; t < BH+2; t++) {
        const int r = rStart + t;
        float4 cur = nCur; float Lcw = nLw, Rcx = nRx;
        nCur = Z; nLw = 0.f; nRx = 0.f;
        {
            int rn = r + 1;
            if (rn <= rEnd && (unsigned)rn < (unsigned)H) {
                const float* p = sk + rn*W + colBase;
                float4 q = *(const float4*)p;
                nCur = make_float4(1.f-q.x, 1.f-q.y, 1.f-q.z, 1.f-q.w);
                if (isL && !edgeL) nLw = 1.f - p[-1];
                if (isR && !edgeR) nRx = 1.f - p[4];
            }
        }
        int k = r-1;
        if (k >= R0row && k < R0row+BH) {
            float4 vs;
            vs.x = i0.x + i1.x + cur.x;
            vs.y = i0.y + i1.y + cur.y;
            vs.z = i0.z + i1.z + cur.z;
            vs.w = i0.w + i1.w + cur.w;
            float vsL = L0w + L1w + Lcw;
            float vsR = R0x + R1x + Rcx;
            float sm1 = __shfl_up_sync(0xffffffffu, vs.w, 1); if (isL) sm1 = vsL;
            float sp1 = __shfl_down_sync(0xffffffffu, vs.x, 1); if (isR) sp1 = vsR;
            float ns0 = sm1 + vs.x + vs.y + 9.f*i1.x;
            float ns1 = vs.x + vs.y + vs.z + 9.f*i1.y;
            float ns2 = vs.y + vs.z + vs.w + 9.f*i1.z;
            float ns3 = vs.z + vs.w + sp1 + 9.f*i1.w;
            float d0 = ns0 - 11.f, d1 = ns1 - 11.f, d2 = ns2 - 11.f, d3 = ns3 - 11.f;
            float e0 = __expf(-d0*d0) * i1.x;
            float e1 = __expf(-d1*d1) * i1.y;
            float e2 = __expf(-d2*d2) * i1.z;
            float e3 = __expf(-d3*d3) * i1.w;
            float es = e0 + e1 + e2 + e3;
            s0 += es;
            sy += es * (float)k;
            sx += e0*(float)colBase + e1*(float)(colBase+1)
                + e2*(float)(colBase+2) + e3*(float)(colBase+3);
        }
        i0=i1; i1=cur; L0w=L1w; L1w=Lcw; R0x=R1x; R1x=Rcx;
    }

    __shared__ float s[3][128];
    s[0][threadIdx.x] = s0; s[1][threadIdx.x] = sy; s[2][threadIdx.x] = sx;
    __syncthreads();
    for (int off = 64; off > 0; off >>= 1) {
        if (threadIdx.x < off) {
            s[0][threadIdx.x] += s[0][threadIdx.x + off];
            s[1][threadIdx.x] += s[1][threadIdx.x + off];
            s[2][threadIdx.x] += s[2][threadIdx.x + off];
        }
        __syncthreads();
    }
    if (threadIdx.x == 0) {
        int o = (img*NBANDS + blockIdx.x)*3;
        g_epPart[o + 0] = s[0][0];
        g_epPart[o + 1] = s[1][0];
        g_epPart[o + 2] = s[2][0];
    }
}

// ---------------------------------------------------------------------------
// final: combine everything into the scalar loss.
// ---------------------------------------------------------------------------
__global__ __launch_bounds__(256) void final_kernel(float* __restrict__ out) {
    __shared__ float s[3][256];
    s[0][threadIdx.x] = g_dicePart[threadIdx.x*3 + 0];
    s[1][threadIdx.x] = g_dicePart[threadIdx.x*3 + 1];
    s[2][threadIdx.x] = g_dicePart[threadIdx.x*3 + 2];
    __syncthreads();
    for (int off = 128; off > 0; off >>= 1) {
        if (threadIdx.x < off) {
            s[0][threadIdx.x] += s[0][threadIdx.x + off];
            s[1][threadIdx.x] += s[1][threadIdx.x + off];
            s[2][threadIdx.x] += s[2][threadIdx.x + off];
        }
        __syncthreads();
    }
    __shared__ float S[NIMG], SY[NIMG], SX[NIMG];
    if (threadIdx.x < NIMG) {
        float t0 = 0.f, t1 = 0.f, t2 = 0.f;
        for (int bd = 0; bd < NBANDS; bd++) {
            int o = (threadIdx.x*NBANDS + bd)*3;
            t0 += g_epPart[o + 0];
            t1 += g_epPart[o + 1];
            t2 += g_epPart[o + 2];
        }
        S[threadIdx.x] = t0; SY[threadIdx.x] = t1; SX[threadIdx.x] = t2;
    }
    __syncthreads();
    if (threadIdx.x == 0) {
        float inter = s[0][0], sumT = s[1][0], sumP = s[2][0];
        float dice = 1.f - (2.f*inter + 1.f) / (sumT + sumP + 1.f);
        float distsum = 0.f, cntsum = 0.f;
        for (int b = 0; b < NB; b++) {
            float np = S[b], nt = S[NB + b];
            float tp = np + 1e-8f, tt = nt + 1e-8f;
            float ycp = SY[b] / tp,      xcp = SX[b] / tp;
            float yct = SY[NB+b] / tt,   xct = SX[NB+b] / tt;
            float dy = ycp - yct, dx = xcp - xct;
            distsum += sqrtf(dy*dy + dx*dx);
            cntsum  += fabsf(np - nt) / (np + nt + 1e-8f);
        }
        float diag = sqrtf((float)(H*H) + (float)(W*W));
        float distance_loss = (distsum / (float)NB) / (diag * 1.0f + 1e-8f);
        float count_penalty = cntsum / (float)NB;
        out[0] = 0.85f * dice + 0.15f * (distance_loss + count_penalty);
    }
}

// ---------------------------------------------------------------------------
extern "C" void kernel_launch(void* const* d_in, const int* in_sizes, int n_in,
                              void* d_out, int out_size) {
    const float* net = (const float*)d_in[0];
    const int*   yt  = (const int*)d_in[1];
    float* out = (float*)d_out;
    (void)in_sizes; (void)n_in; (void)out_size;

    prep_kernel<<<256, 256>>>(net, yt);

    dim3 grid(NBANDS, NIMG);
    sweep_init_kernel<<<grid, 128>>>();               // q init; img stays in A
    for (int k = 0; k < NFUSED; k++)
        sweep_step2_kernel<<<grid, 128>>>(k & 1);     // 2 iterations per launch
    endpoint_kernel<<<grid, 128>>>();
    final_kernel<<<1, 256>>>(out);
}

// round 12
// speedup vs baseline: 1.3089x; 1.3089x over previous
#include <cuda_runtime.h>
#include <math.h>

#define H 512
#define W 512
#define HW (512*512)
#define NB 8          // batch
#define NIMG 16       // 8 pred + 8 true
#define NUM_ITER 40
#define BH 16
#define NBANDS (H/BH)   // 32
#define BIGF 3.0e38f
#define PREP_BLOCKS 512

// ---- scratch (device globals; no allocation) ----
// g_skel stores q = 1 - skel  (multiplicative form: q *= (1 - delta))
__device__ float g_imgA[(size_t)NIMG*HW];
__device__ float g_imgB[(size_t)NIMG*HW];
__device__ float g_skel[(size_t)NIMG*HW];
__device__ float g_dicePart[PREP_BLOCKS*3];   // [block][inter,sumT,sumP]
__device__ float g_epPart[NIMG*NBANDS*3];     // [img][band][s,sy,sx]

__device__ __forceinline__ float f3min(float a,float b,float c){return fminf(fminf(a,b),c);}
__device__ __forceinline__ float f3max(float a,float b,float c){return fmaxf(fmaxf(a,b),c);}

// ---------------------------------------------------------------------------
// prep: prob = sigmoid(x1-x0); true->float; dice partials.
// 512 blocks x 256 threads; block bb owns segment (bb&63) of image (bb>>6).
// All traffic vectorized (float4/int4); no per-pixel division.
// Exact coverage: 8 imgs * 64 segs * 256 thr * 4 float4 = NB*HW/4.
// ---------------------------------------------------------------------------
__global__ __launch_bounds__(256) void prep_kernel(const float* __restrict__ net,
                                                   const int* __restrict__ yt) {
    const int b   = blockIdx.x >> 6;          // image 0..7
    const int seg = blockIdx.x & 63;          // segment 0..63
    const int tid = threadIdx.x;
    const float4* x0p = (const float4*)(net + (size_t)b*2*HW);
    const float4* x1p = (const float4*)(net + (size_t)b*2*HW + HW);
    const int4*   ytp = (const int4*)(yt + (size_t)b*HW);
    float4* probp = (float4*)(g_imgA + (size_t)b*HW);
    float4* truep = (float4*)(g_imgA + (size_t)(NB + b)*HW);

    float inter = 0.f, st = 0.f, sp = 0.f;
    #pragma unroll
    for (int j = 0; j < 4; j++) {
        int i = seg*1024 + j*256 + tid;       // float4 index within image
        float4 x0 = x0p[i];
        float4 x1 = x1p[i];
        int4 ti = ytp[i];
        float4 pr;
        pr.x = 1.f / (1.f + __expf(x0.x - x1.x));
        pr.y = 1.f / (1.f + __expf(x0.y - x1.y));
        pr.z = 1.f / (1.f + __expf(x0.z - x1.z));
        pr.w = 1.f / (1.f + __expf(x0.w - x1.w));
        float4 tf = make_float4((float)ti.x, (float)ti.y, (float)ti.z, (float)ti.w);
        probp[i] = pr;
        truep[i] = tf;
        inter += tf.x*pr.x + tf.y*pr.y + tf.z*pr.z + tf.w*pr.w;
        st += tf.x + tf.y + tf.z + tf.w;
        sp += pr.x + pr.y + pr.z + pr.w;
    }
    __shared__ float s[3][256];
    s[0][tid] = inter; s[1][tid] = st; s[2][tid] = sp;
    __syncthreads();
    for (int off = 128; off > 0; off >>= 1) {
        if (tid < off) {
            s[0][tid] += s[0][tid + off];
            s[1][tid] += s[1][tid + off];
            s[2][tid] += s[2][tid + off];
        }
        __syncthreads();
    }
    if (tid == 0) {
        g_dicePart[blockIdx.x*3 + 0] = s[0][0];
        g_dicePart[blockIdx.x*3 + 1] = s[1][0];
        g_dicePart[blockIdx.x*3 + 2] = s[2][0];
    }
}

// ---------------------------------------------------------------------------
// INIT sweep: q = 1 - relu(img - dilate3x3(erode(img))).  (single launch)
// ---------------------------------------------------------------------------
__global__ __launch_bounds__(128) void sweep_init_kernel() {
    const int img = blockIdx.y;
    const int R0row = blockIdx.x * BH;
    const int lane = threadIdx.x & 31;
    const int colBase = ((threadIdx.x >> 5) << 7) + (lane << 2);
    const bool isL = (lane == 0), isR = (lane == 31);
    const bool edgeL = (colBase == 0), edgeR = (colBase == W-4);
    const float* __restrict__ in = g_imgA + (size_t)img*HW;
    float* __restrict__ skel = g_skel + (size_t)img*HW;

    const float4 PINF = make_float4(BIGF,BIGF,BIGF,BIGF);
    float4 i0=PINF, i1=PINF, L0=PINF, L1=PINF, Rv0=PINF, Rv1=PINF;
    float4 hp=PINF; float hpL1=BIGF, hpR0=BIGF;
    float4 e1a=make_float4(-BIGF,-BIGF,-BIGF,-BIGF), e1b=e1a;
    float e1aL=-BIGF, e1bL=-BIGF, e1aR=-BIGF, e1bR=-BIGF;

    const int rStart = R0row-2, rEnd = R0row+BH+1;   // BH+4 = 20 rows
    float4 nCur=PINF, nL=PINF, nR=PINF;
    if (rStart >= 0 && rStart < H) {
        const float* p = in + rStart*W + colBase;
        nCur = *(const float4*)p;
        if (isL && !edgeL) nL = *(const float4*)(p - 4);
        if (isR && !edgeR) nR = *(const float4*)(p + 4);
    }

    #pragma unroll 2
    for (int t = 0; t < BH+4; t++) {
        const int r = rStart + t;
        float4 cur = nCur, Lc = nL, Rc = nR;
        nCur = PINF; nL = PINF; nR = PINF;
        {
            int rn = r + 1;
            if (rn <= rEnd && (unsigned)rn < (unsigned)H) {
                const float* p = in + rn*W + colBase;
                nCur = *(const float4*)p;
                if (isL && !edgeL) nL = *(const float4*)(p - 4);
                if (isR && !edgeR) nR = *(const float4*)(p + 4);
            }
        }
        float xm1 = __shfl_up_sync(0xffffffffu, cur.w, 1); if (isL) xm1 = Lc.w;
        float xp1 = __shfl_down_sync(0xffffffffu, cur.x, 1); if (isR) xp1 = Rc.x;
        float4 hc;
        hc.x = f3min(xm1, cur.x, cur.y);
        hc.y = f3min(cur.x, cur.y, cur.z);
        hc.z = f3min(cur.y, cur.z, cur.w);
        hc.w = f3min(cur.z, cur.w, xp1);
        float hcL1 = f3min(Lc.z, Lc.w, cur.x);
        float hcR0 = f3min(cur.w, Rc.x, Rc.y);

        float4 e1n;
        e1n.x = fminf(f3min(i0.x,i1.x,cur.x), hp.x);
        e1n.y = fminf(f3min(i0.y,i1.y,cur.y), hp.y);
        e1n.z = fminf(f3min(i0.z,i1.z,cur.z), hp.z);
        e1n.w = fminf(f3min(i0.w,i1.w,cur.w), hp.w);
        float e1nL = fminf(f3min(L0.w,L1.w,Lc.w), hpL1);
        float e1nR = fminf(f3min(Rv0.x,Rv1.x,Rc.x), hpR0);
        {
            int k = r-1;
            if (k < 0 || k >= H) {
                e1n = make_float4(-BIGF,-BIGF,-BIGF,-BIGF);
                e1nL = e1nR = -BIGF;
            }
        }
        if (edgeL) e1nL = -BIGF;
        if (edgeR) e1nR = -BIGF;

        if (t >= 4) {   // r >= R0row+2
            float4 mv;
            mv.x = f3max(e1a.x, e1b.x, e1n.x);
            mv.y = f3max(e1a.y, e1b.y, e1n.y);
            mv.z = f3max(e1a.z, e1b.z, e1n.z);
            mv.w = f3max(e1a.w, e1b.w, e1n.w);
            float mvL = f3max(e1aL, e1bL, e1nL);
            float mvR = f3max(e1aR, e1bR, e1nR);
            float mm1 = __shfl_up_sync(0xffffffffu, mv.w, 1); if (isL) mm1 = mvL;
            float mp1 = __shfl_down_sync(0xffffffffu, mv.x, 1); if (isR) mp1 = mvR;
            float4 open;
            open.x = f3max(mm1, mv.x, mv.y);
            open.y = f3max(mv.x, mv.y, mv.z);
            open.z = f3max(mv.y, mv.z, mv.w);
            open.w = f3max(mv.z, mv.w, mp1);
            int k2 = r-2;
            float4 s;
            s.x = 1.f - fmaxf(i0.x - open.x, 0.f);
            s.y = 1.f - fmaxf(i0.y - open.y, 0.f);
            s.z = 1.f - fmaxf(i0.z - open.z, 0.f);
            s.w = 1.f - fmaxf(i0.w - open.w, 0.f);
            *(float4*)(skel + k2*W + colBase) = s;
        }
        i0=i1; i1=cur; L0=L1; L1=Lc; Rv0=Rv1; Rv1=Rc;
        hp=hc; hpL1=hcL1; hpR0=hcR0;
        e1a=e1b; e1b=e1n; e1aL=e1bL; e1bL=e1nL; e1aR=e1bR; e1bR=e1nR;
    }
}

// ---------------------------------------------------------------------------
// STEP body, templated on BOUNDARY. Interior bands (1..30): all row checks
// removed. q update: q *= (1 - delta) (one FFMA per pixel).
// writeImg=false on the final iteration (output image never read again).
// ---------------------------------------------------------------------------
template<bool BOUNDARY>
__device__ __forceinline__ void step_body(
    const float* __restrict__ in, float* __restrict__ outImg,
    float* __restrict__ skel, int R0row, int colBase,
    bool isL, bool isR, bool edgeL, bool edgeR, bool writeImg)
{
    const float4 PINF = make_float4(BIGF,BIGF,BIGF,BIGF);
    const float4 NINF = make_float4(-BIGF,-BIGF,-BIGF,-BIGF);

    float4 i0=PINF, i1=PINF, L0=PINF, L1=PINF, Rv0=PINF, Rv1=PINF;
    float4 hp=PINF; float hpL0=BIGF, hpL1=BIGF, hpR0=BIGF, hpR1=BIGF;
    float4 e1a=PINF, e1b=PINF; float e1aL=BIGF, e1bL=BIGF, e1aR=BIGF, e1bR=BIGF;
    float4 h1p=PINF; float h1pL=BIGF, h1pR=BIGF;
    float4 e2a=NINF, e2b=NINF; float e2aL=-BIGF, e2bL=-BIGF, e2aR=-BIGF, e2bR=-BIGF;

    const int rStart = R0row-3, rEnd = R0row+BH+2;   // BH+6 = 22 rows
    float4 nCur=PINF, nL=PINF, nR=PINF, nSk=make_float4(0,0,0,0);
    if (!BOUNDARY || (rStart >= 0 && rStart < H)) {
        const float* p = in + rStart*W + colBase;
        nCur = *(const float4*)p;
        if (isL && !edgeL) nL = *(const float4*)(p - 4);
        if (isR && !edgeR) nR = *(const float4*)(p + 4);
    }

    #pragma unroll 2
    for (int t = 0; t < BH+6; t++) {
        const int r = rStart + t;
        float4 cur = nCur, Lc = nL, Rc = nR, skv = nSk;
        {
            int rn = r + 1;
            if (BOUNDARY) {
                nCur = PINF; nL = PINF; nR = PINF;
                if (rn <= rEnd && (unsigned)rn < (unsigned)H) {
                    const float* p = in + rn*W + colBase;
                    nCur = *(const float4*)p;
                    if (isL && !edgeL) nL = *(const float4*)(p - 4);
                    if (isR && !edgeR) nR = *(const float4*)(p + 4);
                }
                if (rn >= R0row+3 && rn <= rEnd)
                    nSk = *(const float4*)(skel + (rn-3)*W + colBase);
            } else {
                const float* p = in + rn*W + colBase;
                nCur = *(const float4*)p;
                nL = PINF; nR = PINF;
                if (isL && !edgeL) nL = *(const float4*)(p - 4);
                if (isR && !edgeR) nR = *(const float4*)(p + 4);
                nSk = *(const float4*)(skel + (rn-3)*W + colBase);
            }
        }
        // hmin3 of img row r (own cols + halo cols -2,-1,128,129)
        float xm1 = __shfl_up_sync(0xffffffffu, cur.w, 1); if (isL) xm1 = Lc.w;
        float xp1 = __shfl_down_sync(0xffffffffu, cur.x, 1); if (isR) xp1 = Rc.x;
        float4 hc;
        hc.x = f3min(xm1, cur.x, cur.y);
        hc.y = f3min(cur.x, cur.y, cur.z);
        hc.z = f3min(cur.y, cur.z, cur.w);
        hc.w = f3min(cur.z, cur.w, xp1);
        float hcL0 = f3min(Lc.y, Lc.z, Lc.w);
        float hcL1 = f3min(Lc.z, Lc.w, cur.x);
        float hcR0 = f3min(cur.w, Rc.x, Rc.y);
        float hcR1 = f3min(Rc.x, Rc.y, Rc.z);

        // e1 = erode(img) at row r-1 (feeds erode -> OOB = +INF)
        float4 e1n;
        e1n.x = fminf(f3min(i0.x,i1.x,cur.x), hp.x);
        e1n.y = fminf(f3min(i0.y,i1.y,cur.y), hp.y);
        e1n.z = fminf(f3min(i0.z,i1.z,cur.z), hp.z);
        e1n.w = fminf(f3min(i0.w,i1.w,cur.w), hp.w);
        float e1nL0 = fminf(f3min(L0.z,L1.z,Lc.z), hpL0);   // col -2
        float e1nL1 = fminf(f3min(L0.w,L1.w,Lc.w), hpL1);   // col -1
        float e1nR0 = fminf(f3min(Rv0.x,Rv1.x,Rc.x), hpR0); // col 128
        float e1nR1 = fminf(f3min(Rv0.y,Rv1.y,Rc.y), hpR1); // col 129
        if (BOUNDARY) {
            int k = r-1;
            if (k < 0 || k >= H) { e1n = PINF; e1nL0=e1nL1=e1nR0=e1nR1=BIGF; }
        }
        // hmin3 of e1 at row r-1 (cols -1..128)
        float em1 = __shfl_up_sync(0xffffffffu, e1n.w, 1); if (isL) em1 = e1nL1;
        float ep1 = __shfl_down_sync(0xffffffffu, e1n.x, 1); if (isR) ep1 = e1nR0;
        float4 h1c;
        h1c.x = f3min(em1, e1n.x, e1n.y);
        h1c.y = f3min(e1n.x, e1n.y, e1n.z);
        h1c.z = f3min(e1n.y, e1n.z, e1n.w);
        h1c.w = f3min(e1n.z, e1n.w, ep1);
        float h1cL = f3min(e1nL0, e1nL1, e1n.x);   // col -1
        float h1cR = f3min(e1n.w, e1nR0, e1nR1);   // col 128

        // e2 = erode(e1) at row r-2 (feeds dilate -> OOB = -INF)
        float4 e2n;
        e2n.x = fminf(f3min(e1a.x,e1b.x,e1n.x), h1p.x);
        e2n.y = fminf(f3min(e1a.y,e1b.y,e1n.y), h1p.y);
        e2n.z = fminf(f3min(e1a.z,e1b.z,e1n.z), h1p.z);
        e2n.w = fminf(f3min(e1a.w,e1b.w,e1n.w), h1p.w);
        float e2nL = fminf(f3min(e1aL,e1bL,e1nL1), h1pL);
        float e2nR = fminf(f3min(e1aR,e1bR,e1nR0), h1pR);
        if (BOUNDARY) {
            int j = r-2;
            if (j < 0 || j >= H) { e2n = NINF; e2nL = e2nR = -BIGF; }
        }
        if (edgeL) e2nL = -BIGF;
        if (edgeR) e2nR = -BIGF;

        // out row r-3: open = dilate3x3(e2); delta = relu(e1 - open); q *= (1-delta)
        if (t >= 6) {   // r >= R0row+3
            float4 mv;
            mv.x = f3max(e2a.x, e2b.x, e2n.x);
            mv.y = f3max(e2a.y, e2b.y, e2n.y);
            mv.z = f3max(e2a.z, e2b.z, e2n.z);
            mv.w = f3max(e2a.w, e2b.w, e2n.w);
            float mvL = f3max(e2aL, e2bL, e2nL);
            float mvR = f3max(e2aR, e2bR, e2nR);
            float mm1 = __shfl_up_sync(0xffffffffu, mv.w, 1); if (isL) mm1 = mvL;
            float mp1 = __shfl_down_sync(0xffffffffu, mv.x, 1); if (isR) mp1 = mvR;
            float4 open;
            open.x = f3max(mm1, mv.x, mv.y);
            open.y = f3max(mv.x, mv.y, mv.z);
            open.z = f3max(mv.y, mv.z, mv.w);
            open.w = f3max(mv.z, mv.w, mp1);
            int k2 = r-3;
            float4 ec = e1a;   // e1 row r-3 (oldest in window)
            float4 q = skv;
            float d0 = fmaxf(ec.x - open.x, 0.f); q.x -= q.x*d0;
            float d1 = fmaxf(ec.y - open.y, 0.f); q.y -= q.y*d1;
            float d2 = fmaxf(ec.z - open.z, 0.f); q.z -= q.z*d2;
            float d3 = fmaxf(ec.w - open.w, 0.f); q.w -= q.w*d3;
            *(float4*)(skel + k2*W + colBase) = q;
            if (writeImg)
                *(float4*)(outImg + k2*W + colBase) = ec;
        }
        // rotate windows (renamed away under unroll)
        i0=i1; i1=cur; L0=L1; L1=Lc; Rv0=Rv1; Rv1=Rc;
        hp=hc; hpL0=hcL0; hpL1=hcL1; hpR0=hcR0; hpR1=hcR1;
        e1a=e1b; e1b=e1n; e1aL=e1bL; e1bL=e1nL1; e1aR=e1bR; e1bR=e1nR0;
        h1p=h1c; h1pL=h1cL; h1pR=h1cR;
        e2a=e2b; e2b=e2n; e2aL=e2bL; e2bL=e2nL; e2aR=e2bR; e2bR=e2nR;
    }
}

__global__ __launch_bounds__(128) void sweep_step_kernel(int bufsel, int writeImg) {
    const int img = blockIdx.y;
    const int band = blockIdx.x;
    const int R0row = band * BH;
    const int lane = threadIdx.x & 31;
    const int colBase = ((threadIdx.x >> 5) << 7) + (lane << 2);
    const bool isL = (lane == 0), isR = (lane == 31);
    const bool edgeL = (colBase == 0), edgeR = (colBase == W-4);
    const float* __restrict__ in     = (bufsel ? g_imgB : g_imgA) + (size_t)img*HW;
    float*       __restrict__ outImg = (bufsel ? g_imgA : g_imgB) + (size_t)img*HW;
    float*       __restrict__ skel   = g_skel + (size_t)img*HW;

    if (band == 0 || band == NBANDS-1)
        step_body<true >(in, outImg, skel, R0row, colBase, isL, isR, edgeL, edgeR, writeImg != 0);
    else
        step_body<false>(in, outImg, skel, R0row, colBase, isL, isR, edgeL, edgeR, writeImg != 0);
}

// ---------------------------------------------------------------------------
// endpoints: skel = 1 - q on load; ns = sum3x3(skel) + 9*center (zero pad);
// ep = exp(-(ns-11)^2)*center; partial sums per (img, band).
// ---------------------------------------------------------------------------
__global__ __launch_bounds__(128) void endpoint_kernel() {
    const int img = blockIdx.y;
    const int R0row = blockIdx.x * BH;
    const int lane = threadIdx.x & 31;
    const int colBase = ((threadIdx.x >> 5) << 7) + (lane << 2);
    const bool isL = (lane == 0), isR = (lane == 31);
    const bool edgeL = (colBase == 0), edgeR = (colBase == W-4);
    const float* __restrict__ sk = g_skel + (size_t)img*HW;

    const float4 Z = make_float4(0.f,0.f,0.f,0.f);
    float4 i0=Z, i1=Z; float L0w=0.f,L1w=0.f,R0x=0.f,R1x=0.f;
    float s0=0.f, sy=0.f, sx=0.f;

    const int rStart = R0row-1, rEnd = R0row+BH;    // BH+2 = 18 rows
    float4 nCur=Z; float nLw=0.f, nRx=0.f;
    if (rStart >= 0 && rStart < H) {
        const float* p = sk + rStart*W + colBase;
        float4 q = *(const float4*)p;
        nCur = make_float4(1.f-q.x, 1.f-q.y, 1.f-q.z, 1.f-q.w);
        if (isL && !edgeL) nLw = 1.f - p[-1];
        if (isR && !edgeR) nRx = 1.f - p[4];
    }

    #pragma unroll 2
    for (int t = 0; t < BH+2; t++) {
        const int r = rStart + t;
        float4 cur = nCur; float Lcw = nLw, Rcx = nRx;
        nCur = Z; nLw = 0.f; nRx = 0.f;
        {
            int rn = r + 1;
            if (rn <= rEnd && (unsigned)rn < (unsigned)H) {
                const float* p = sk + rn*W + colBase;
                float4 q = *(const float4*)p;
                nCur = make_float4(1.f-q.x, 1.f-q.y, 1.f-q.z, 1.f-q.w);
                if (isL && !edgeL) nLw = 1.f - p[-1];
                if (isR && !edgeR) nRx = 1.f - p[4];
            }
        }
        int k = r-1;
        if (k >= R0row && k < R0row+BH) {
            float4 vs;
            vs.x = i0.x + i1.x + cur.x;
            vs.y = i0.y + i1.y + cur.y;
            vs.z = i0.z + i1.z + cur.z;
            vs.w = i0.w + i1.w + cur.w;
            float vsL = L0w + L1w + Lcw;
            float vsR = R0x + R1x + Rcx;
            float sm1 = __shfl_up_sync(0xffffffffu, vs.w, 1); if (isL) sm1 = vsL;
            float sp1 = __shfl_down_sync(0xffffffffu, vs.x, 1); if (isR) sp1 = vsR;
            float ns0 = sm1 + vs.x + vs.y + 9.f*i1.x;
            float ns1 = vs.x + vs.y + vs.z + 9.f*i1.y;
            float ns2 = vs.y + vs.z + vs.w + 9.f*i1.z;
            float ns3 = vs.z + vs.w + sp1 + 9.f*i1.w;
            float d0 = ns0 - 11.f, d1 = ns1 - 11.f, d2 = ns2 - 11.f, d3 = ns3 - 11.f;
            float e0 = __expf(-d0*d0) * i1.x;
            float e1 = __expf(-d1*d1) * i1.y;
            float e2 = __expf(-d2*d2) * i1.z;
            float e3 = __expf(-d3*d3) * i1.w;
            float es = e0 + e1 + e2 + e3;
            s0 += es;
            sy += es * (float)k;
            sx += e0*(float)colBase + e1*(float)(colBase+1)
                + e2*(float)(colBase+2) + e3*(float)(colBase+3);
        }
        i0=i1; i1=cur; L0w=L1w; L1w=Lcw; R0x=R1x; R1x=Rcx;
    }

    __shared__ float s[3][128];
    s[0][threadIdx.x] = s0; s[1][threadIdx.x] = sy; s[2][threadIdx.x] = sx;
    __syncthreads();
    for (int off = 64; off > 0; off >>= 1) {
        if (threadIdx.x < off) {
            s[0][threadIdx.x] += s[0][threadIdx.x + off];
            s[1][threadIdx.x] += s[1][threadIdx.x + off];
            s[2][threadIdx.x] += s[2][threadIdx.x + off];
        }
        __syncthreads();
    }
    if (threadIdx.x == 0) {
        int o = (img*NBANDS + blockIdx.x)*3;
        g_epPart[o + 0] = s[0][0];
        g_epPart[o + 1] = s[1][0];
        g_epPart[o + 2] = s[2][0];
    }
}

// ---------------------------------------------------------------------------
// final: combine everything into the scalar loss. (512 dice partials now)
// ---------------------------------------------------------------------------
__global__ __launch_bounds__(256) void final_kernel(float* __restrict__ out) {
    __shared__ float s[3][256];
    {
        int i0 = threadIdx.x, i1 = threadIdx.x + 256;
        s[0][threadIdx.x] = g_dicePart[i0*3 + 0] + g_dicePart[i1*3 + 0];
        s[1][threadIdx.x] = g_dicePart[i0*3 + 1] + g_dicePart[i1*3 + 1];
        s[2][threadIdx.x] = g_dicePart[i0*3 + 2] + g_dicePart[i1*3 + 2];
    }
    __syncthreads();
    for (int off = 128; off > 0; off >>= 1) {
        if (threadIdx.x < off) {
            s[0][threadIdx.x] += s[0][threadIdx.x + off];
            s[1][threadIdx.x] += s[1][threadIdx.x + off];
            s[2][threadIdx.x] += s[2][threadIdx.x + off];
        }
        __syncthreads();
    }
    __shared__ float S[NIMG], SY[NIMG], SX[NIMG];
    if (threadIdx.x < NIMG) {
        float t0 = 0.f, t1 = 0.f, t2 = 0.f;
        for (int bd = 0; bd < NBANDS; bd++) {
            int o = (threadIdx.x*NBANDS + bd)*3;
            t0 += g_epPart[o + 0];
            t1 += g_epPart[o + 1];
            t2 += g_epPart[o + 2];
        }
        S[threadIdx.x] = t0; SY[threadIdx.x] = t1; SX[threadIdx.x] = t2;
    }
    __syncthreads();
    if (threadIdx.x == 0) {
        float inter = s[0][0], sumT = s[1][0], sumP = s[2][0];
        float dice = 1.f - (2.f*inter + 1.f) / (sumT + sumP + 1.f);
        float distsum = 0.f, cntsum = 0.f;
        for (int b = 0; b < NB; b++) {
            float np = S[b], nt = S[NB + b];
            float tp = np + 1e-8f, tt = nt + 1e-8f;
            float ycp = SY[b] / tp,      xcp = SX[b] / tp;
            float yct = SY[NB+b] / tt,   xct = SX[NB+b] / tt;
            float dy = ycp - yct, dx = xcp - xct;
            distsum += sqrtf(dy*dy + dx*dx);
            cntsum  += fabsf(np - nt) / (np + nt + 1e-8f);
        }
        float diag = sqrtf((float)(H*H) + (float)(W*W));
        float distance_loss = (distsum / (float)NB) / (diag * 1.0f + 1e-8f);
        float count_penalty = cntsum / (float)NB;
        out[0] = 0.85f * dice + 0.15f * (distance_loss + count_penalty);
    }
}

// ---------------------------------------------------------------------------
extern "C" void kernel_launch(void* const* d_in, const int* in_sizes, int n_in,
                              void* d_out, int out_size) {
    const float* net = (const float*)d_in[0];
    const int*   yt  = (const int*)d_in[1];
    float* out = (float*)d_out;
    (void)in_sizes; (void)n_in; (void)out_size;

    prep_kernel<<<PREP_BLOCKS, 256>>>(net, yt);

    dim3 grid(NBANDS, NIMG);
    sweep_init_kernel<<<grid, 128>>>();             // q init; img stays in A
    for (int i = 0; i < NUM_ITER; i++)
        sweep_step_kernel<<<grid, 128>>>(i & 1, (i < NUM_ITER-1) ? 1 : 0);
    endpoint_kernel<<<grid, 128>>>();
    final_kernel<<<1, 256>>>(out);
}

// round 13
// speedup vs baseline: 1.3974x; 1.0676x over previous
#include <cuda_runtime.h>
#include <math.h>

#define H 512
#define W 512
#define HW (512*512)
#define NB 8          // batch
#define NIMG 16       // 8 pred + 8 true
#define NUM_ITER 40
#define BH 16
#define NBANDS (H/BH)   // 32
#define BIGF 3.0e38f
#define PREP_BLOCKS 512

// ---- scratch (device globals; no allocation) ----
// g_skel stores q = 1 - skel  (multiplicative form: q *= (1 - delta))
__device__ float g_imgA[(size_t)NIMG*HW];
__device__ float g_imgB[(size_t)NIMG*HW];
__device__ float g_skel[(size_t)NIMG*HW];
__device__ float g_dicePart[PREP_BLOCKS*3];   // [block][inter,sumT,sumP]
__device__ float g_epPart[NIMG*NBANDS*3];     // [img][band][s,sy,sx]

__device__ __forceinline__ float f3min(float a,float b,float c){return fminf(fminf(a,b),c);}
__device__ __forceinline__ float f3max(float a,float b,float c){return fmaxf(fmaxf(a,b),c);}

// ---------------------------------------------------------------------------
// prep: prob = sigmoid(x1-x0); true->float; dice partials. (vectorized)
// ---------------------------------------------------------------------------
__global__ __launch_bounds__(256) void prep_kernel(const float* __restrict__ net,
                                                   const int* __restrict__ yt) {
    const int b   = blockIdx.x >> 6;          // image 0..7
    const int seg = blockIdx.x & 63;          // segment 0..63
    const int tid = threadIdx.x;
    const float4* x0p = (const float4*)(net + (size_t)b*2*HW);
    const float4* x1p = (const float4*)(net + (size_t)b*2*HW + HW);
    const int4*   ytp = (const int4*)(yt + (size_t)b*HW);
    float4* probp = (float4*)(g_imgA + (size_t)b*HW);
    float4* truep = (float4*)(g_imgA + (size_t)(NB + b)*HW);

    float inter = 0.f, st = 0.f, sp = 0.f;
    #pragma unroll
    for (int j = 0; j < 4; j++) {
        int i = seg*1024 + j*256 + tid;       // float4 index within image
        float4 x0 = x0p[i];
        float4 x1 = x1p[i];
        int4 ti = ytp[i];
        float4 pr;
        pr.x = 1.f / (1.f + __expf(x0.x - x1.x));
        pr.y = 1.f / (1.f + __expf(x0.y - x1.y));
        pr.z = 1.f / (1.f + __expf(x0.z - x1.z));
        pr.w = 1.f / (1.f + __expf(x0.w - x1.w));
        float4 tf = make_float4((float)ti.x, (float)ti.y, (float)ti.z, (float)ti.w);
        probp[i] = pr;
        truep[i] = tf;
        inter += tf.x*pr.x + tf.y*pr.y + tf.z*pr.z + tf.w*pr.w;
        st += tf.x + tf.y + tf.z + tf.w;
        sp += pr.x + pr.y + pr.z + pr.w;
    }
    __shared__ float s[3][256];
    s[0][tid] = inter; s[1][tid] = st; s[2][tid] = sp;
    __syncthreads();
    for (int off = 128; off > 0; off >>= 1) {
        if (tid < off) {
            s[0][tid] += s[0][tid + off];
            s[1][tid] += s[1][tid + off];
            s[2][tid] += s[2][tid + off];
        }
        __syncthreads();
    }
    if (tid == 0) {
        g_dicePart[blockIdx.x*3 + 0] = s[0][0];
        g_dicePart[blockIdx.x*3 + 1] = s[1][0];
        g_dicePart[blockIdx.x*3 + 2] = s[2][0];
    }
}

// ---------------------------------------------------------------------------
// INIT sweep: q = 1 - relu(img - dilate3x3(erode(img))).  (single launch)
// ---------------------------------------------------------------------------
__global__ __launch_bounds__(128) void sweep_init_kernel() {
    const int img = blockIdx.y;
    const int R0row = blockIdx.x * BH;
    const int lane = threadIdx.x & 31;
    const int colBase = ((threadIdx.x >> 5) << 7) + (lane << 2);
    const bool isL = (lane == 0), isR = (lane == 31);
    const bool edgeL = (colBase == 0), edgeR = (colBase == W-4);
    const float* __restrict__ in = g_imgA + (size_t)img*HW;
    float* __restrict__ skel = g_skel + (size_t)img*HW;

    const float4 PINF = make_float4(BIGF,BIGF,BIGF,BIGF);
    float4 i0=PINF, i1=PINF, L0=PINF, L1=PINF, Rv0=PINF, Rv1=PINF;
    float4 hp=PINF; float hpL1=BIGF, hpR0=BIGF;
    float4 e1a=make_float4(-BIGF,-BIGF,-BIGF,-BIGF), e1b=e1a;
    float e1aL=-BIGF, e1bL=-BIGF, e1aR=-BIGF, e1bR=-BIGF;

    const int rStart = R0row-2, rEnd = R0row+BH+1;   // BH+4 = 20 rows
    float4 nCur=PINF, nL=PINF, nR=PINF;
    if (rStart >= 0 && rStart < H) {
        const float* p = in + rStart*W + colBase;
        nCur = *(const float4*)p;
        if (isL && !edgeL) nL = *(const float4*)(p - 4);
        if (isR && !edgeR) nR = *(const float4*)(p + 4);
    }

    #pragma unroll 2
    for (int t = 0; t < BH+4; t++) {
        const int r = rStart + t;
        float4 cur = nCur, Lc = nL, Rc = nR;
        nCur = PINF; nL = PINF; nR = PINF;
        {
            int rn = r + 1;
            if (rn <= rEnd && (unsigned)rn < (unsigned)H) {
                const float* p = in + rn*W + colBase;
                nCur = *(const float4*)p;
                if (isL && !edgeL) nL = *(const float4*)(p - 4);
                if (isR && !edgeR) nR = *(const float4*)(p + 4);
            }
        }
        float xm1 = __shfl_up_sync(0xffffffffu, cur.w, 1); if (isL) xm1 = Lc.w;
        float xp1 = __shfl_down_sync(0xffffffffu, cur.x, 1); if (isR) xp1 = Rc.x;
        float4 hc;
        hc.x = f3min(xm1, cur.x, cur.y);
        hc.y = f3min(cur.x, cur.y, cur.z);
        hc.z = f3min(cur.y, cur.z, cur.w);
        hc.w = f3min(cur.z, cur.w, xp1);
        float hcL1 = f3min(Lc.z, Lc.w, cur.x);
        float hcR0 = f3min(cur.w, Rc.x, Rc.y);

        float4 e1n;
        e1n.x = fminf(f3min(i0.x,i1.x,cur.x), hp.x);
        e1n.y = fminf(f3min(i0.y,i1.y,cur.y), hp.y);
        e1n.z = fminf(f3min(i0.z,i1.z,cur.z), hp.z);
        e1n.w = fminf(f3min(i0.w,i1.w,cur.w), hp.w);
        float e1nL = fminf(f3min(L0.w,L1.w,Lc.w), hpL1);
        float e1nR = fminf(f3min(Rv0.x,Rv1.x,Rc.x), hpR0);
        {
            int k = r-1;
            if (k < 0 || k >= H) {
                e1n = make_float4(-BIGF,-BIGF,-BIGF,-BIGF);
                e1nL = e1nR = -BIGF;
            }
        }
        if (edgeL) e1nL = -BIGF;
        if (edgeR) e1nR = -BIGF;

        if (t >= 4) {   // r >= R0row+2
            float4 mv;
            mv.x = f3max(e1a.x, e1b.x, e1n.x);
            mv.y = f3max(e1a.y, e1b.y, e1n.y);
            mv.z = f3max(e1a.z, e1b.z, e1n.z);
            mv.w = f3max(e1a.w, e1b.w, e1n.w);
            float mvL = f3max(e1aL, e1bL, e1nL);
            float mvR = f3max(e1aR, e1bR, e1nR);
            float mm1 = __shfl_up_sync(0xffffffffu, mv.w, 1); if (isL) mm1 = mvL;
            float mp1 = __shfl_down_sync(0xffffffffu, mv.x, 1); if (isR) mp1 = mvR;
            float4 open;
            open.x = f3max(mm1, mv.x, mv.y);
            open.y = f3max(mv.x, mv.y, mv.z);
            open.z = f3max(mv.y, mv.z, mv.w);
            open.w = f3max(mv.z, mv.w, mp1);
            int k2 = r-2;
            float4 s;
            s.x = 1.f - fmaxf(i0.x - open.x, 0.f);
            s.y = 1.f - fmaxf(i0.y - open.y, 0.f);
            s.z = 1.f - fmaxf(i0.z - open.z, 0.f);
            s.w = 1.f - fmaxf(i0.w - open.w, 0.f);
            *(float4*)(skel + k2*W + colBase) = s;
        }
        i0=i1; i1=cur; L0=L1; L1=Lc; Rv0=Rv1; Rv1=Rc;
        hp=hc; hpL1=hcL1; hpR0=hcR0;
        e1a=e1b; e1b=e1n; e1aL=e1bL; e1bL=e1nL; e1aR=e1bR; e1bR=e1nR;
    }
}

// ---------------------------------------------------------------------------
// STEP body, templated on BOUNDARY + UNROLL factor. Interior bands: all row
// checks removed, loop FULLY UNROLLED (BH+6 = 22 constant) so rotation MOVs,
// loop branches, and per-row address IMADs vanish. Boundary bands: unroll 2.
// q update: q *= (1 - delta) (one FFMA per pixel).
// ---------------------------------------------------------------------------
template<bool BOUNDARY, int UNROLL>
__device__ __forceinline__ void step_body(
    const float* __restrict__ in, float* __restrict__ outImg,
    float* __restrict__ skel, int R0row, int colBase,
    bool isL, bool isR, bool edgeL, bool edgeR, bool writeImg)
{
    const float4 PINF = make_float4(BIGF,BIGF,BIGF,BIGF);
    const float4 NINF = make_float4(-BIGF,-BIGF,-BIGF,-BIGF);

    float4 i0=PINF, i1=PINF, L0=PINF, L1=PINF, Rv0=PINF, Rv1=PINF;
    float4 hp=PINF; float hpL0=BIGF, hpL1=BIGF, hpR0=BIGF, hpR1=BIGF;
    float4 e1a=PINF, e1b=PINF; float e1aL=BIGF, e1bL=BIGF, e1aR=BIGF, e1bR=BIGF;
    float4 h1p=PINF; float h1pL=BIGF, h1pR=BIGF;
    float4 e2a=NINF, e2b=NINF; float e2aL=-BIGF, e2bL=-BIGF, e2aR=-BIGF, e2bR=-BIGF;

    const int rStart = R0row-3, rEnd = R0row+BH+2;   // BH+6 = 22 rows
    float4 nCur=PINF, nL=PINF, nR=PINF, nSk=make_float4(0,0,0,0);
    if (!BOUNDARY || (rStart >= 0 && rStart < H)) {
        const float* p = in + rStart*W + colBase;
        nCur = *(const float4*)p;
        if (isL && !edgeL) nL = *(const float4*)(p - 4);
        if (isR && !edgeR) nR = *(const float4*)(p + 4);
    }

    #pragma unroll UNROLL
    for (int t = 0; t < BH+6; t++) {
        const int r = rStart + t;
        float4 cur = nCur, Lc = nL, Rc = nR, skv = nSk;
        {
            int rn = r + 1;
            if (BOUNDARY) {
                nCur = PINF; nL = PINF; nR = PINF;
                if (rn <= rEnd && (unsigned)rn < (unsigned)H) {
                    const float* p = in + rn*W + colBase;
                    nCur = *(const float4*)p;
                    if (isL && !edgeL) nL = *(const float4*)(p - 4);
                    if (isR && !edgeR) nR = *(const float4*)(p + 4);
                }
                if (rn >= R0row+3 && rn <= rEnd)
                    nSk = *(const float4*)(skel + (rn-3)*W + colBase);
            } else {
                const float* p = in + rn*W + colBase;
                nCur = *(const float4*)p;
                nL = PINF; nR = PINF;
                if (isL && !edgeL) nL = *(const float4*)(p - 4);
                if (isR && !edgeR) nR = *(const float4*)(p + 4);
                nSk = *(const float4*)(skel + (rn-3)*W + colBase);
            }
        }
        // hmin3 of img row r (own cols + halo cols -2,-1,128,129)
        float xm1 = __shfl_up_sync(0xffffffffu, cur.w, 1); if (isL) xm1 = Lc.w;
        float xp1 = __shfl_down_sync(0xffffffffu, cur.x, 1); if (isR) xp1 = Rc.x;
        float4 hc;
        hc.x = f3min(xm1, cur.x, cur.y);
        hc.y = f3min(cur.x, cur.y, cur.z);
        hc.z = f3min(cur.y, cur.z, cur.w);
        hc.w = f3min(cur.z, cur.w, xp1);
        float hcL0 = f3min(Lc.y, Lc.z, Lc.w);
        float hcL1 = f3min(Lc.z, Lc.w, cur.x);
        float hcR0 = f3min(cur.w, Rc.x, Rc.y);
        float hcR1 = f3min(Rc.x, Rc.y, Rc.z);

        // e1 = erode(img) at row r-1 (feeds erode -> OOB = +INF)
        float4 e1n;
        e1n.x = fminf(f3min(i0.x,i1.x,cur.x), hp.x);
        e1n.y = fminf(f3min(i0.y,i1.y,cur.y), hp.y);
        e1n.z = fminf(f3min(i0.z,i1.z,cur.z), hp.z);
        e1n.w = fminf(f3min(i0.w,i1.w,cur.w), hp.w);
        float e1nL0 = fminf(f3min(L0.z,L1.z,Lc.z), hpL0);   // col -2
        float e1nL1 = fminf(f3min(L0.w,L1.w,Lc.w), hpL1);   // col -1
        float e1nR0 = fminf(f3min(Rv0.x,Rv1.x,Rc.x), hpR0); // col 128
        float e1nR1 = fminf(f3min(Rv0.y,Rv1.y,Rc.y), hpR1); // col 129
        if (BOUNDARY) {
            int k = r-1;
            if (k < 0 || k >= H) { e1n = PINF; e1nL0=e1nL1=e1nR0=e1nR1=BIGF; }
        }
        // hmin3 of e1 at row r-1 (cols -1..128)
        float em1 = __shfl_up_sync(0xffffffffu, e1n.w, 1); if (isL) em1 = e1nL1;
        float ep1 = __shfl_down_sync(0xffffffffu, e1n.x, 1); if (isR) ep1 = e1nR0;
        float4 h1c;
        h1c.x = f3min(em1, e1n.x, e1n.y);
        h1c.y = f3min(e1n.x, e1n.y, e1n.z);
        h1c.z = f3min(e1n.y, e1n.z, e1n.w);
        h1c.w = f3min(e1n.z, e1n.w, ep1);
        float h1cL = f3min(e1nL0, e1nL1, e1n.x);   // col -1
        float h1cR = f3min(e1n.w, e1nR0, e1nR1);   // col 128

        // e2 = erode(e1) at row r-2 (feeds dilate -> OOB = -INF)
        float4 e2n;
        e2n.x = fminf(f3min(e1a.x,e1b.x,e1n.x), h1p.x);
        e2n.y = fminf(f3min(e1a.y,e1b.y,e1n.y), h1p.y);
        e2n.z = fminf(f3min(e1a.z,e1b.z,e1n.z), h1p.z);
        e2n.w = fminf(f3min(e1a.w,e1b.w,e1n.w), h1p.w);
        float e2nL = fminf(f3min(e1aL,e1bL,e1nL1), h1pL);
        float e2nR = fminf(f3min(e1aR,e1bR,e1nR0), h1pR);
        if (BOUNDARY) {
            int j = r-2;
            if (j < 0 || j >= H) { e2n = NINF; e2nL = e2nR = -BIGF; }
        }
        if (edgeL) e2nL = -BIGF;
        if (edgeR) e2nR = -BIGF;

        // out row r-3: open = dilate3x3(e2); delta = relu(e1 - open); q *= (1-delta)
        if (t >= 6) {   // r >= R0row+3
            float4 mv;
            mv.x = f3max(e2a.x, e2b.x, e2n.x);
            mv.y = f3max(e2a.y, e2b.y, e2n.y);
            mv.z = f3max(e2a.z, e2b.z, e2n.z);
            mv.w = f3max(e2a.w, e2b.w, e2n.w);
            float mvL = f3max(e2aL, e2bL, e2nL);
            float mvR = f3max(e2aR, e2bR, e2nR);
            float mm1 = __shfl_up_sync(0xffffffffu, mv.w, 1); if (isL) mm1 = mvL;
            float mp1 = __shfl_down_sync(0xffffffffu, mv.x, 1); if (isR) mp1 = mvR;
            float4 open;
            open.x = f3max(mm1, mv.x, mv.y);
            open.y = f3max(mv.x, mv.y, mv.z);
            open.z = f3max(mv.y, mv.z, mv.w);
            open.w = f3max(mv.z, mv.w, mp1);
            int k2 = r-3;
            float4 ec = e1a;   // e1 row r-3 (oldest in window)
            float4 q = skv;
            float d0 = fmaxf(ec.x - open.x, 0.f); q.x -= q.x*d0;
            float d1 = fmaxf(ec.y - open.y, 0.f); q.y -= q.y*d1;
            float d2 = fmaxf(ec.z - open.z, 0.f); q.z -= q.z*d2;
            float d3 = fmaxf(ec.w - open.w, 0.f); q.w -= q.w*d3;
            *(float4*)(skel + k2*W + colBase) = q;
            if (writeImg)
                *(float4*)(outImg + k2*W + colBase) = ec;
        }
        // rotate windows (renamed away under unroll)
        i0=i1; i1=cur; L0=L1; L1=Lc; Rv0=Rv1; Rv1=Rc;
        hp=hc; hpL0=hcL0; hpL1=hcL1; hpR0=hcR0; hpR1=hcR1;
        e1a=e1b; e1b=e1n; e1aL=e1bL; e1bL=e1nL1; e1aR=e1bR; e1bR=e1nR0;
        h1p=h1c; h1pL=h1cL; h1pR=h1cR;
        e2a=e2b; e2b=e2n; e2aL=e2bL; e2bL=e2nL; e2aR=e2bR; e2bR=e2nR;
    }
}

__global__ __launch_bounds__(128) void sweep_step_kernel(int bufsel, int writeImg) {
    const int img = blockIdx.y;
    const int band = blockIdx.x;
    const int R0row = band * BH;
    const int lane = threadIdx.x & 31;
    const int colBase = ((threadIdx.x >> 5) << 7) + (lane << 2);
    const bool isL = (lane == 0), isR = (lane == 31);
    const bool edgeL = (colBase == 0), edgeR = (colBase == W-4);
    const float* __restrict__ in     = (bufsel ? g_imgB : g_imgA) + (size_t)img*HW;
    float*       __restrict__ outImg = (bufsel ? g_imgA : g_imgB) + (size_t)img*HW;
    float*       __restrict__ skel   = g_skel + (size_t)img*HW;

    if (band == 0 || band == NBANDS-1)
        step_body<true, 2>(in, outImg, skel, R0row, colBase, isL, isR, edgeL, edgeR, writeImg != 0);
    else
        step_body<false, BH+6>(in, outImg, skel, R0row, colBase, isL, isR, edgeL, edgeR, writeImg != 0);
}

// ---------------------------------------------------------------------------
// endpoints: skel = 1 - q on load; ns = sum3x3(skel) + 9*center (zero pad);
// ep = exp(-(ns-11)^2)*center; partial sums per (img, band). Fully unrolled.
// ---------------------------------------------------------------------------
__global__ __launch_bounds__(128) void endpoint_kernel() {
    const int img = blockIdx.y;
    const int R0row = blockIdx.x * BH;
    const int lane = threadIdx.x & 31;
    const int colBase = ((threadIdx.x >> 5) << 7) + (lane << 2);
    const bool isL = (lane == 0), isR = (lane == 31);
    const bool edgeL = (colBase == 0), edgeR = (colBase == W-4);
    const float* __restrict__ sk = g_skel + (size_t)img*HW;

    const float4 Z = make_float4(0.f,0.f,0.f,0.f);
    float4 i0=Z, i1=Z; float L0w=0.f,L1w=0.f,R0x=0.f,R1x=0.f;
    float s0=0.f, sy=0.f, sx=0.f;

    const int rStart = R0row-1, rEnd = R0row+BH;    // BH+2 = 18 rows
    float4 nCur=Z; float nLw=0.f, nRx=0.f;
    if (rStart >= 0 && rStart < H) {
        const float* p = sk + rStart*W + colBase;
        float4 q = *(const float4*)p;
        nCur = make_float4(1.f-q.x, 1.f-q.y, 1.f-q.z, 1.f-q.w);
        if (isL && !edgeL) nLw = 1.f - p[-1];
        if (isR && !edgeR) nRx = 1.f - p[4];
    }

    #pragma unroll
    for (int t = 0; t < BH+2; t++) {
        const int r = rStart + t;
        float4 cur = nCur; float Lcw = nLw, Rcx = nRx;
        nCur = Z; nLw = 0.f; nRx = 0.f;
        {
            int rn = r + 1;
            if (rn <= rEnd && (unsigned)rn < (unsigned)H) {
                const float* p = sk + rn*W + colBase;
                float4 q = *(const float4*)p;
                nCur = make_float4(1.f-q.x, 1.f-q.y, 1.f-q.z, 1.f-q.w);
                if (isL && !edgeL) nLw = 1.f - p[-1];
                if (isR && !edgeR) nRx = 1.f - p[4];
            }
        }
        int k = r-1;
        if (k >= R0row && k < R0row+BH) {
            float4 vs;
            vs.x = i0.x + i1.x + cur.x;
            vs.y = i0.y + i1.y + cur.y;
            vs.z = i0.z + i1.z + cur.z;
            vs.w = i0.w + i1.w + cur.w;
            float vsL = L0w + L1w + Lcw;
            float vsR = R0x + R1x + Rcx;
            float sm1 = __shfl_up_sync(0xffffffffu, vs.w, 1); if (isL) sm1 = vsL;
            float sp1 = __shfl_down_sync(0xffffffffu, vs.x, 1); if (isR) sp1 = vsR;
            float ns0 = sm1 + vs.x + vs.y + 9.f*i1.x;
            float ns1 = vs.x + vs.y + vs.z + 9.f*i1.y;
            float ns2 = vs.y + vs.z + vs.w + 9.f*i1.z;
            float ns3 = vs.z + vs.w + sp1 + 9.f*i1.w;
            float d0 = ns0 - 11.f, d1 = ns1 - 11.f, d2 = ns2 - 11.f, d3 = ns3 - 11.f;
            float e0 = __expf(-d0*d0) * i1.x;
            float e1 = __expf(-d1*d1) * i1.y;
            float e2 = __expf(-d2*d2) * i1.z;
            float e3 = __expf(-d3*d3) * i1.w;
            float es = e0 + e1 + e2 + e3;
            s0 += es;
            sy += es * (float)k;
            sx += e0*(float)colBase + e1*(float)(colBase+1)
                + e2*(float)(colBase+2) + e3*(float)(colBase+3);
        }
        i0=i1; i1=cur; L0w=L1w; L1w=Lcw; R0x=R1x; R1x=Rcx;
    }

    __shared__ float s[3][128];
    s[0][threadIdx.x] = s0; s[1][threadIdx.x] = sy; s[2][threadIdx.x] = sx;
    __syncthreads();
    for (int off = 64; off > 0; off >>= 1) {
        if (threadIdx.x < off) {
            s[0][threadIdx.x] += s[0][threadIdx.x + off];
            s[1][threadIdx.x] += s[1][threadIdx.x + off];
            s[2][threadIdx.x] += s[2][threadIdx.x + off];
        }
        __syncthreads();
    }
    if (threadIdx.x == 0) {
        int o = (img*NBANDS + blockIdx.x)*3;
        g_epPart[o + 0] = s[0][0];
        g_epPart[o + 1] = s[1][0];
        g_epPart[o + 2] = s[2][0];
    }
}

// ---------------------------------------------------------------------------
// final: combine everything into the scalar loss. (512 dice partials)
// ---------------------------------------------------------------------------
__global__ __launch_bounds__(256) void final_kernel(float* __restrict__ out) {
    __shared__ float s[3][256];
    {
        int i0 = threadIdx.x, i1 = threadIdx.x + 256;
        s[0][threadIdx.x] = g_dicePart[i0*3 + 0] + g_dicePart[i1*3 + 0];
        s[1][threadIdx.x] = g_dicePart[i0*3 + 1] + g_dicePart[i1*3 + 1];
        s[2][threadIdx.x] = g_dicePart[i0*3 + 2] + g_dicePart[i1*3 + 2];
    }
    __syncthreads();
    for (int off = 128; off > 0; off >>= 1) {
        if (threadIdx.x < off) {
            s[0][threadIdx.x] += s[0][threadIdx.x + off];
            s[1][threadIdx.x] += s[1][threadIdx.x + off];
            s[2][threadIdx.x] += s[2][threadIdx.x + off];
        }
        __syncthreads();
    }
    __shared__ float S[NIMG], SY[NIMG], SX[NIMG];
    if (threadIdx.x < NIMG) {
        float t0 = 0.f, t1 = 0.f, t2 = 0.f;
        for (int bd = 0; bd < NBANDS; bd++) {
            int o = (threadIdx.x*NBANDS + bd)*3;
            t0 += g_epPart[o + 0];
            t1 += g_epPart[o + 1];
            t2 += g_epPart[o + 2];
        }
        S[threadIdx.x] = t0; SY[threadIdx.x] = t1; SX[threadIdx.x] = t2;
    }
    __syncthreads();
    if (threadIdx.x == 0) {
        float inter = s[0][0], sumT = s[1][0], sumP = s[2][0];
        float dice = 1.f - (2.f*inter + 1.f) / (sumT + sumP + 1.f);
        float distsum = 0.f, cntsum = 0.f;
        for (int b = 0; b < NB; b++) {
            float np = S[b], nt = S[NB + b];
            float tp = np + 1e-8f, tt = nt + 1e-8f;
            float ycp = SY[b] / tp,      xcp = SX[b] / tp;
            float yct = SY[NB+b] / tt,   xct = SX[NB+b] / tt;
            float dy = ycp - yct, dx = xcp - xct;
            distsum += sqrtf(dy*dy + dx*dx);
            cntsum  += fabsf(np - nt) / (np + nt + 1e-8f);
        }
        float diag = sqrtf((float)(H*H) + (float)(W*W));
        float distance_loss = (distsum / (float)NB) / (diag * 1.0f + 1e-8f);
        float count_penalty = cntsum / (float)NB;
        out[0] = 0.85f * dice + 0.15f * (distance_loss + count_penalty);
    }
}

// ---------------------------------------------------------------------------
extern "C" void kernel_launch(void* const* d_in, const int* in_sizes, int n_in,
                              void* d_out, int out_size) {
    const float* net = (const float*)d_in[0];
    const int*   yt  = (const int*)d_in[1];
    float* out = (float*)d_out;
    (void)in_sizes; (void)n_in; (void)out_size;

    prep_kernel<<<PREP_BLOCKS, 256>>>(net, yt);

    dim3 grid(NBANDS, NIMG);
    sweep_init_kernel<<<grid, 128>>>();             // q init; img stays in A
    for (int i = 0; i < NUM_ITER; i++)
        sweep_step_kernel<<<grid, 128>>>(i & 1, (i < NUM_ITER-1) ? 1 : 0);
    endpoint_kernel<<<grid, 128>>>();
    final_kernel<<<1, 256>>>(out);
}

// round 14
// speedup vs baseline: 1.8601x; 1.3311x over previous
#include <cuda_runtime.h>
#include <math.h>

#define H 512
#define W 512
#define HW (512*512)
#define NB 8          // batch
#define NIMG 16       // 8 pred + 8 true
#define NUM_ITER 40
#define BH 16
#define NBANDS (H/BH)   // 32
#define BIGF 3.0e38f
#define PREP_BLOCKS 512

// ---- scratch (device globals; no allocation) ----
// g_skel stores q = 1 - skel  (multiplicative form: q *= (1 - delta))
__device__ float g_imgA[(size_t)NIMG*HW];
__device__ float g_imgB[(size_t)NIMG*HW];
__device__ float g_skel[(size_t)NIMG*HW];
__device__ float g_dicePart[PREP_BLOCKS*3];   // [block][inter,sumT,sumP]
__device__ float g_epPart[NIMG*NBANDS*3];     // [img][band][s,sy,sx]

__device__ __forceinline__ float f3min(float a,float b,float c){return fminf(fminf(a,b),c);}
__device__ __forceinline__ float f3max(float a,float b,float c){return fmaxf(fmaxf(a,b),c);}

// ---------------------------------------------------------------------------
// prep: prob = sigmoid(x1-x0); true->float; dice partials. (vectorized)
// ---------------------------------------------------------------------------
__global__ __launch_bounds__(256) void prep_kernel(const float* __restrict__ net,
                                                   const int* __restrict__ yt) {
    const int b   = blockIdx.x >> 6;          // image 0..7
    const int seg = blockIdx.x & 63;          // segment 0..63
    const int tid = threadIdx.x;
    const float4* x0p = (const float4*)(net + (size_t)b*2*HW);
    const float4* x1p = (const float4*)(net + (size_t)b*2*HW + HW);
    const int4*   ytp = (const int4*)(yt + (size_t)b*HW);
    float4* probp = (float4*)(g_imgA + (size_t)b*HW);
    float4* truep = (float4*)(g_imgA + (size_t)(NB + b)*HW);

    float inter = 0.f, st = 0.f, sp = 0.f;
    #pragma unroll
    for (int j = 0; j < 4; j++) {
        int i = seg*1024 + j*256 + tid;       // float4 index within image
        float4 x0 = x0p[i];
        float4 x1 = x1p[i];
        int4 ti = ytp[i];
        float4 pr;
        pr.x = 1.f / (1.f + __expf(x0.x - x1.x));
        pr.y = 1.f / (1.f + __expf(x0.y - x1.y));
        pr.z = 1.f / (1.f + __expf(x0.z - x1.z));
        pr.w = 1.f / (1.f + __expf(x0.w - x1.w));
        float4 tf = make_float4((float)ti.x, (float)ti.y, (float)ti.z, (float)ti.w);
        probp[i] = pr;
        truep[i] = tf;
        inter += tf.x*pr.x + tf.y*pr.y + tf.z*pr.z + tf.w*pr.w;
        st += tf.x + tf.y + tf.z + tf.w;
        sp += pr.x + pr.y + pr.z + pr.w;
    }
    __shared__ float s[3][256];
    s[0][tid] = inter; s[1][tid] = st; s[2][tid] = sp;
    __syncthreads();
    for (int off = 128; off > 0; off >>= 1) {
        if (tid < off) {
            s[0][tid] += s[0][tid + off];
            s[1][tid] += s[1][tid + off];
            s[2][tid] += s[2][tid + off];
        }
        __syncthreads();
    }
    if (tid == 0) {
        g_dicePart[blockIdx.x*3 + 0] = s[0][0];
        g_dicePart[blockIdx.x*3 + 1] = s[1][0];
        g_dicePart[blockIdx.x*3 + 2] = s[2][0];
    }
}

// ---------------------------------------------------------------------------
// INIT sweep: q = 1 - relu(img - dilate3x3(erode(img))). FULLY UNROLLED.
// ---------------------------------------------------------------------------
__global__ __launch_bounds__(128, 4) void sweep_init_kernel() {
    const int img = blockIdx.y;
    const int R0row = blockIdx.x * BH;
    const int lane = threadIdx.x & 31;
    const int colBase = ((threadIdx.x >> 5) << 7) + (lane << 2);
    const bool isL = (lane == 0), isR = (lane == 31);
    const bool edgeL = (colBase == 0), edgeR = (colBase == W-4);
    const float* __restrict__ in = g_imgA + (size_t)img*HW;
    float* __restrict__ skel = g_skel + (size_t)img*HW;

    const float4 PINF = make_float4(BIGF,BIGF,BIGF,BIGF);
    float4 i0=PINF, i1=PINF, L0=PINF, L1=PINF, Rv0=PINF, Rv1=PINF;
    float4 hp=PINF; float hpL1=BIGF, hpR0=BIGF;
    float4 e1a=make_float4(-BIGF,-BIGF,-BIGF,-BIGF), e1b=e1a;
    float e1aL=-BIGF, e1bL=-BIGF, e1aR=-BIGF, e1bR=-BIGF;

    const int rStart = R0row-2, rEnd = R0row+BH+1;   // BH+4 = 20 rows
    float4 nCur=PINF, nL=PINF, nR=PINF;
    if (rStart >= 0 && rStart < H) {
        const float* p = in + rStart*W + colBase;
        nCur = *(const float4*)p;
        if (isL && !edgeL) nL = *(const float4*)(p - 4);
        if (isR && !edgeR) nR = *(const float4*)(p + 4);
    }

    #pragma unroll
    for (int t = 0; t < BH+4; t++) {
        const int r = rStart + t;
        float4 cur = nCur, Lc = nL, Rc = nR;
        nCur = PINF; nL = PINF; nR = PINF;
        {
            int rn = r + 1;
            if (rn <= rEnd && (unsigned)rn < (unsigned)H) {
                const float* p = in + rn*W + colBase;
                nCur = *(const float4*)p;
                if (isL && !edgeL) nL = *(const float4*)(p - 4);
                if (isR && !edgeR) nR = *(const float4*)(p + 4);
            }
        }
        float xm1 = __shfl_up_sync(0xffffffffu, cur.w, 1); if (isL) xm1 = Lc.w;
        float xp1 = __shfl_down_sync(0xffffffffu, cur.x, 1); if (isR) xp1 = Rc.x;
        float4 hc;
        hc.x = f3min(xm1, cur.x, cur.y);
        hc.y = f3min(cur.x, cur.y, cur.z);
        hc.z = f3min(cur.y, cur.z, cur.w);
        hc.w = f3min(cur.z, cur.w, xp1);
        float hcL1 = f3min(Lc.z, Lc.w, cur.x);
        float hcR0 = f3min(cur.w, Rc.x, Rc.y);

        float4 e1n;
        e1n.x = fminf(f3min(i0.x,i1.x,cur.x), hp.x);
        e1n.y = fminf(f3min(i0.y,i1.y,cur.y), hp.y);
        e1n.z = fminf(f3min(i0.z,i1.z,cur.z), hp.z);
        e1n.w = fminf(f3min(i0.w,i1.w,cur.w), hp.w);
        float e1nL = fminf(f3min(L0.w,L1.w,Lc.w), hpL1);
        float e1nR = fminf(f3min(Rv0.x,Rv1.x,Rc.x), hpR0);
        {
            int k = r-1;
            if (k < 0 || k >= H) {
                e1n = make_float4(-BIGF,-BIGF,-BIGF,-BIGF);
                e1nL = e1nR = -BIGF;
            }
        }
        if (edgeL) e1nL = -BIGF;
        if (edgeR) e1nR = -BIGF;

        if (t >= 4) {   // r >= R0row+2
            float4 mv;
            mv.x = f3max(e1a.x, e1b.x, e1n.x);
            mv.y = f3max(e1a.y, e1b.y, e1n.y);
            mv.z = f3max(e1a.z, e1b.z, e1n.z);
            mv.w = f3max(e1a.w, e1b.w, e1n.w);
            float mvL = f3max(e1aL, e1bL, e1nL);
            float mvR = f3max(e1aR, e1bR, e1nR);
            float mm1 = __shfl_up_sync(0xffffffffu, mv.w, 1); if (isL) mm1 = mvL;
            float mp1 = __shfl_down_sync(0xffffffffu, mv.x, 1); if (isR) mp1 = mvR;
            float4 open;
            open.x = f3max(mm1, mv.x, mv.y);
            open.y = f3max(mv.x, mv.y, mv.z);
            open.z = f3max(mv.y, mv.z, mv.w);
            open.w = f3max(mv.z, mv.w, mp1);
            int k2 = r-2;
            float4 s;
            s.x = 1.f - fmaxf(i0.x - open.x, 0.f);
            s.y = 1.f - fmaxf(i0.y - open.y, 0.f);
            s.z = 1.f - fmaxf(i0.z - open.z, 0.f);
            s.w = 1.f - fmaxf(i0.w - open.w, 0.f);
            *(float4*)(skel + k2*W + colBase) = s;
        }
        i0=i1; i1=cur; L0=L1; L1=Lc; Rv0=Rv1; Rv1=Rc;
        hp=hc; hpL1=hcL1; hpR0=hcR0;
        e1a=e1b; e1b=e1n; e1aL=e1bL; e1bL=e1nL; e1aR=e1bR; e1bR=e1nR;
    }
}

// ---------------------------------------------------------------------------
// STEP body, templated on BOUNDARY. FULLY UNROLLED for both variants:
// rotation MOVs, loop branches, and per-row address IMADs vanish.
// Interior bands additionally drop all row checks.
// q update: q *= (1 - delta) (one FFMA per pixel).
// ---------------------------------------------------------------------------
template<bool BOUNDARY>
__device__ __forceinline__ void step_body(
    const float* __restrict__ in, float* __restrict__ outImg,
    float* __restrict__ skel, int R0row, int colBase,
    bool isL, bool isR, bool edgeL, bool edgeR, bool writeImg)
{
    const float4 PINF = make_float4(BIGF,BIGF,BIGF,BIGF);
    const float4 NINF = make_float4(-BIGF,-BIGF,-BIGF,-BIGF);

    float4 i0=PINF, i1=PINF, L0=PINF, L1=PINF, Rv0=PINF, Rv1=PINF;
    float4 hp=PINF; float hpL0=BIGF, hpL1=BIGF, hpR0=BIGF, hpR1=BIGF;
    float4 e1a=PINF, e1b=PINF; float e1aL=BIGF, e1bL=BIGF, e1aR=BIGF, e1bR=BIGF;
    float4 h1p=PINF; float h1pL=BIGF, h1pR=BIGF;
    float4 e2a=NINF, e2b=NINF; float e2aL=-BIGF, e2bL=-BIGF, e2aR=-BIGF, e2bR=-BIGF;

    const int rStart = R0row-3, rEnd = R0row+BH+2;   // BH+6 = 22 rows
    float4 nCur=PINF, nL=PINF, nR=PINF, nSk=make_float4(0,0,0,0);
    if (!BOUNDARY || (rStart >= 0 && rStart < H)) {
        const float* p = in + rStart*W + colBase;
        nCur = *(const float4*)p;
        if (isL && !edgeL) nL = *(const float4*)(p - 4);
        if (isR && !edgeR) nR = *(const float4*)(p + 4);
    }

    #pragma unroll
    for (int t = 0; t < BH+6; t++) {
        const int r = rStart + t;
        float4 cur = nCur, Lc = nL, Rc = nR, skv = nSk;
        {
            int rn = r + 1;
            if (BOUNDARY) {
                nCur = PINF; nL = PINF; nR = PINF;
                if (rn <= rEnd && (unsigned)rn < (unsigned)H) {
                    const float* p = in + rn*W + colBase;
                    nCur = *(const float4*)p;
                    if (isL && !edgeL) nL = *(const float4*)(p - 4);
                    if (isR && !edgeR) nR = *(const float4*)(p + 4);
                }
                if (rn >= R0row+3 && rn <= rEnd)
                    nSk = *(const float4*)(skel + (rn-3)*W + colBase);
            } else {
                const float* p = in + rn*W + colBase;
                nCur = *(const float4*)p;
                nL = PINF; nR = PINF;
                if (isL && !edgeL) nL = *(const float4*)(p - 4);
                if (isR && !edgeR) nR = *(const float4*)(p + 4);
                nSk = *(const float4*)(skel + (rn-3)*W + colBase);
            }
        }
        // hmin3 of img row r (own cols + halo cols -2,-1,128,129)
        float xm1 = __shfl_up_sync(0xffffffffu, cur.w, 1); if (isL) xm1 = Lc.w;
        float xp1 = __shfl_down_sync(0xffffffffu, cur.x, 1); if (isR) xp1 = Rc.x;
        float4 hc;
        hc.x = f3min(xm1, cur.x, cur.y);
        hc.y = f3min(cur.x, cur.y, cur.z);
        hc.z = f3min(cur.y, cur.z, cur.w);
        hc.w = f3min(cur.z, cur.w, xp1);
        float hcL0 = f3min(Lc.y, Lc.z, Lc.w);
        float hcL1 = f3min(Lc.z, Lc.w, cur.x);
        float hcR0 = f3min(cur.w, Rc.x, Rc.y);
        float hcR1 = f3min(Rc.x, Rc.y, Rc.z);

        // e1 = erode(img) at row r-1 (feeds erode -> OOB = +INF)
        float4 e1n;
        e1n.x = fminf(f3min(i0.x,i1.x,cur.x), hp.x);
        e1n.y = fminf(f3min(i0.y,i1.y,cur.y), hp.y);
        e1n.z = fminf(f3min(i0.z,i1.z,cur.z), hp.z);
        e1n.w = fminf(f3min(i0.w,i1.w,cur.w), hp.w);
        float e1nL0 = fminf(f3min(L0.z,L1.z,Lc.z), hpL0);   // col -2
        float e1nL1 = fminf(f3min(L0.w,L1.w,Lc.w), hpL1);   // col -1
        float e1nR0 = fminf(f3min(Rv0.x,Rv1.x,Rc.x), hpR0); // col 128
        float e1nR1 = fminf(f3min(Rv0.y,Rv1.y,Rc.y), hpR1); // col 129
        if (BOUNDARY) {
            int k = r-1;
            if (k < 0 || k >= H) { e1n = PINF; e1nL0=e1nL1=e1nR0=e1nR1=BIGF; }
        }
        // hmin3 of e1 at row r-1 (cols -1..128)
        float em1 = __shfl_up_sync(0xffffffffu, e1n.w, 1); if (isL) em1 = e1nL1;
        float ep1 = __shfl_down_sync(0xffffffffu, e1n.x, 1); if (isR) ep1 = e1nR0;
        float4 h1c;
        h1c.x = f3min(em1, e1n.x, e1n.y);
        h1c.y = f3min(e1n.x, e1n.y, e1n.z);
        h1c.z = f3min(e1n.y, e1n.z, e1n.w);
        h1c.w = f3min(e1n.z, e1n.w, ep1);
        float h1cL = f3min(e1nL0, e1nL1, e1n.x);   // col -1
        float h1cR = f3min(e1n.w, e1nR0, e1nR1);   // col 128

        // e2 = erode(e1) at row r-2 (feeds dilate -> OOB = -INF)
        float4 e2n;
        e2n.x = fminf(f3min(e1a.x,e1b.x,e1n.x), h1p.x);
        e2n.y = fminf(f3min(e1a.y,e1b.y,e1n.y), h1p.y);
        e2n.z = fminf(f3min(e1a.z,e1b.z,e1n.z), h1p.z);
        e2n.w = fminf(f3min(e1a.w,e1b.w,e1n.w), h1p.w);
        float e2nL = fminf(f3min(e1aL,e1bL,e1nL1), h1pL);
        float e2nR = fminf(f3min(e1aR,e1bR,e1nR0), h1pR);
        if (BOUNDARY) {
            int j = r-2;
            if (j < 0 || j >= H) { e2n = NINF; e2nL = e2nR = -BIGF; }
        }
        if (edgeL) e2nL = -BIGF;
        if (edgeR) e2nR = -BIGF;

        // out row r-3: open = dilate3x3(e2); delta = relu(e1 - open); q *= (1-delta)
        if (t >= 6) {   // r >= R0row+3
            float4 mv;
            mv.x = f3max(e2a.x, e2b.x, e2n.x);
            mv.y = f3max(e2a.y, e2b.y, e2n.y);
            mv.z = f3max(e2a.z, e2b.z, e2n.z);
            mv.w = f3max(e2a.w, e2b.w, e2n.w);
            float mvL = f3max(e2aL, e2bL, e2nL);
            float mvR = f3max(e2aR, e2bR, e2nR);
            float mm1 = __shfl_up_sync(0xffffffffu, mv.w, 1); if (isL) mm1 = mvL;
            float mp1 = __shfl_down_sync(0xffffffffu, mv.x, 1); if (isR) mp1 = mvR;
            float4 open;
            open.x = f3max(mm1, mv.x, mv.y);
            open.y = f3max(mv.x, mv.y, mv.z);
            open.z = f3max(mv.y, mv.z, mv.w);
            open.w = f3max(mv.z, mv.w, mp1);
            int k2 = r-3;
            float4 ec = e1a;   // e1 row r-3 (oldest in window)
            float4 q = skv;
            float d0 = fmaxf(ec.x - open.x, 0.f); q.x -= q.x*d0;
            float d1 = fmaxf(ec.y - open.y, 0.f); q.y -= q.y*d1;
            float d2 = fmaxf(ec.z - open.z, 0.f); q.z -= q.z*d2;
            float d3 = fmaxf(ec.w - open.w, 0.f); q.w -= q.w*d3;
            *(float4*)(skel + k2*W + colBase) = q;
            if (writeImg)
                *(float4*)(outImg + k2*W + colBase) = ec;
        }
        // rotate windows (renamed away under full unroll)
        i0=i1; i1=cur; L0=L1; L1=Lc; Rv0=Rv1; Rv1=Rc;
        hp=hc; hpL0=hcL0; hpL1=hcL1; hpR0=hcR0; hpR1=hcR1;
        e1a=e1b; e1b=e1n; e1aL=e1bL; e1bL=e1nL1; e1aR=e1bR; e1bR=e1nR0;
        h1p=h1c; h1pL=h1cL; h1pR=h1cR;
        e2a=e2b; e2b=e2n; e2aL=e2bL; e2bL=e2nL; e2aR=e2bR; e2bR=e2nR;
    }
}

__global__ __launch_bounds__(128, 4) void sweep_step_kernel(int bufsel, int writeImg) {
    const int img = blockIdx.y;
    const int band = blockIdx.x;
    const int R0row = band * BH;
    const int lane = threadIdx.x & 31;
    const int colBase = ((threadIdx.x >> 5) << 7) + (lane << 2);
    const bool isL = (lane == 0), isR = (lane == 31);
    const bool edgeL = (colBase == 0), edgeR = (colBase == W-4);
    const float* __restrict__ in     = (bufsel ? g_imgB : g_imgA) + (size_t)img*HW;
    float*       __restrict__ outImg = (bufsel ? g_imgA : g_imgB) + (size_t)img*HW;
    float*       __restrict__ skel   = g_skel + (size_t)img*HW;

    if (band == 0 || band == NBANDS-1)
        step_body<true >(in, outImg, skel, R0row, colBase, isL, isR, edgeL, edgeR, writeImg != 0);
    else
        step_body<false>(in, outImg, skel, R0row, colBase, isL, isR, edgeL, edgeR, writeImg != 0);
}

// ---------------------------------------------------------------------------
// endpoints: skel = 1 - q on load; ns = sum3x3(skel) + 9*center (zero pad);
// ep = exp(-(ns-11)^2)*center; partial sums per (img, band). Fully unrolled.
// ---------------------------------------------------------------------------
__global__ __launch_bounds__(128) void endpoint_kernel() {
    const int img = blockIdx.y;
    const int R0row = blockIdx.x * BH;
    const int lane = threadIdx.x & 31;
    const int colBase = ((threadIdx.x >> 5) << 7) + (lane << 2);
    const bool isL = (lane == 0), isR = (lane == 31);
    const bool edgeL = (colBase == 0), edgeR = (colBase == W-4);
    const float* __restrict__ sk = g_skel + (size_t)img*HW;

    const float4 Z = make_float4(0.f,0.f,0.f,0.f);
    float4 i0=Z, i1=Z; float L0w=0.f,L1w=0.f,R0x=0.f,R1x=0.f;
    float s0=0.f, sy=0.f, sx=0.f;

    const int rStart = R0row-1, rEnd = R0row+BH;    // BH+2 = 18 rows
    float4 nCur=Z; float nLw=0.f, nRx=0.f;
    if (rStart >= 0 && rStart < H) {
        const float* p = sk + rStart*W + colBase;
        float4 q = *(const float4*)p;
        nCur = make_float4(1.f-q.x, 1.f-q.y, 1.f-q.z, 1.f-q.w);
        if (isL && !edgeL) nLw = 1.f - p[-1];
        if (isR && !edgeR) nRx = 1.f - p[4];
    }

    #pragma unroll
    for (int t = 0; t < BH+2; t++) {
        const int r = rStart + t;
        float4 cur = nCur; float Lcw = nLw, Rcx = nRx;
        nCur = Z; nLw = 0.f; nRx = 0.f;
        {
            int rn = r + 1;
            if (rn <= rEnd && (unsigned)rn < (unsigned)H) {
                const float* p = sk + rn*W + colBase;
                float4 q = *(const float4*)p;
                nCur = make_float4(1.f-q.x, 1.f-q.y, 1.f-q.z, 1.f-q.w);
                if (isL && !edgeL) nLw = 1.f - p[-1];
                if (isR && !edgeR) nRx = 1.f - p[4];
            }
        }
        int k = r-1;
        if (k >= R0row && k < R0row+BH) {
            float4 vs;
            vs.x = i0.x + i1.x + cur.x;
            vs.y = i0.y + i1.y + cur.y;
            vs.z = i0.z + i1.z + cur.z;
            vs.w = i0.w + i1.w + cur.w;
            float vsL = L0w + L1w + Lcw;
            float vsR = R0x + R1x + Rcx;
            float sm1 = __shfl_up_sync(0xffffffffu, vs.w, 1); if (isL) sm1 = vsL;
            float sp1 = __shfl_down_sync(0xffffffffu, vs.x, 1); if (isR) sp1 = vsR;
            float ns0 = sm1 + vs.x + vs.y + 9.f*i1.x;
            float ns1 = vs.x + vs.y + vs.z + 9.f*i1.y;
            float ns2 = vs.y + vs.z + vs.w + 9.f*i1.z;
            float ns3 = vs.z + vs.w + sp1 + 9.f*i1.w;
            float d0 = ns0 - 11.f, d1 = ns1 - 11.f, d2 = ns2 - 11.f, d3 = ns3 - 11.f;
            float e0 = __expf(-d0*d0) * i1.x;
            float e1 = __expf(-d1*d1) * i1.y;
            float e2 = __expf(-d2*d2) * i1.z;
            float e3 = __expf(-d3*d3) * i1.w;
            float es = e0 + e1 + e2 + e3;
            s0 += es;
            sy += es * (float)k;
            sx += e0*(float)colBase + e1*(float)(colBase+1)
                + e2*(float)(colBase+2) + e3*(float)(colBase+3);
        }
        i0=i1; i1=cur; L0w=L1w; L1w=Lcw; R0x=R1x; R1x=Rcx;
    }

    __shared__ float s[3][128];
    s[0][threadIdx.x] = s0; s[1][threadIdx.x] = sy; s[2][threadIdx.x] = sx;
    __syncthreads();
    for (int off = 64; off > 0; off >>= 1) {
        if (threadIdx.x < off) {
            s[0][threadIdx.x] += s[0][threadIdx.x + off];
            s[1][threadIdx.x] += s[1][threadIdx.x + off];
            s[2][threadIdx.x] += s[2][threadIdx.x + off];
        }
        __syncthreads();
    }
    if (threadIdx.x == 0) {
        int o = (img*NBANDS + blockIdx.x)*3;
        g_epPart[o + 0] = s[0][0];
        g_epPart[o + 1] = s[1][0];
        g_epPart[o + 2] = s[2][0];
    }
}

// ---------------------------------------------------------------------------
// final: combine everything into the scalar loss. (512 dice partials)
// ---------------------------------------------------------------------------
__global__ __launch_bounds__(256) void final_kernel(float* __restrict__ out) {
    __shared__ float s[3][256];
    {
        int i0 = threadIdx.x, i1 = threadIdx.x + 256;
        s[0][threadIdx.x] = g_dicePart[i0*3 + 0] + g_dicePart[i1*3 + 0];
        s[1][threadIdx.x] = g_dicePart[i0*3 + 1] + g_dicePart[i1*3 + 1];
        s[2][threadIdx.x] = g_dicePart[i0*3 + 2] + g_dicePart[i1*3 + 2];
    }
    __syncthreads();
    for (int off = 128; off > 0; off >>= 1) {
        if (threadIdx.x < off) {
            s[0][threadIdx.x] += s[0][threadIdx.x + off];
            s[1][threadIdx.x] += s[1][threadIdx.x + off];
            s[2][threadIdx.x] += s[2][threadIdx.x + off];
        }
        __syncthreads();
    }
    __shared__ float S[NIMG], SY[NIMG], SX[NIMG];
    if (threadIdx.x < NIMG) {
        float t0 = 0.f, t1 = 0.f, t2 = 0.f;
        for (int bd = 0; bd < NBANDS; bd++) {
            int o = (threadIdx.x*NBANDS + bd)*3;
            t0 += g_epPart[o + 0];
            t1 += g_epPart[o + 1];
            t2 += g_epPart[o + 2];
        }
        S[threadIdx.x] = t0; SY[threadIdx.x] = t1; SX[threadIdx.x] = t2;
    }
    __syncthreads();
    if (threadIdx.x == 0) {
        float inter = s[0][0], sumT = s[1][0], sumP = s[2][0];
        float dice = 1.f - (2.f*inter + 1.f) / (sumT + sumP + 1.f);
        float distsum = 0.f, cntsum = 0.f;
        for (int b = 0; b < NB; b++) {
            float np = S[b], nt = S[NB + b];
            float tp = np + 1e-8f, tt = nt + 1e-8f;
            float ycp = SY[b] / tp,      xcp = SX[b] / tp;
            float yct = SY[NB+b] / tt,   xct = SX[NB+b] / tt;
            float dy = ycp - yct, dx = xcp - xct;
            distsum += sqrtf(dy*dy + dx*dx);
            cntsum  += fabsf(np - nt) / (np + nt + 1e-8f);
        }
        float diag = sqrtf((float)(H*H) + (float)(W*W));
        float distance_loss = (distsum / (float)NB) / (diag * 1.0f + 1e-8f);
        float count_penalty = cntsum / (float)NB;
        out[0] = 0.85f * dice + 0.15f * (distance_loss + count_penalty);
    }
}

// ---------------------------------------------------------------------------
extern "C" void kernel_launch(void* const* d_in, const int* in_sizes, int n_in,
                              void* d_out, int out_size) {
    const float* net = (const float*)d_in[0];
    const int*   yt  = (const int*)d_in[1];
    float* out = (float*)d_out;
    (void)in_sizes; (void)n_in; (void)out_size;

    prep_kernel<<<PREP_BLOCKS, 256>>>(net, yt);

    dim3 grid(NBANDS, NIMG);
    sweep_init_kernel<<<grid, 128>>>();             // q init; img stays in A
    for (int i = 0; i < NUM_ITER; i++)
        sweep_step_kernel<<<grid, 128>>>(i & 1, (i < NUM_ITER-1) ? 1 : 0);
    endpoint_kernel<<<grid, 128>>>();
    final_kernel<<<1, 256>>>(out);
}

// round 15
// speedup vs baseline: 1.9198x; 1.0321x over previous
#include <cuda_runtime.h>
#include <math.h>

#define H 512
#define W 512
#define HW (512*512)
#define NB 8          // batch
#define NIMG 16       // 8 pred + 8 true
#define NUM_ITER 40
#define BH 16
#define NBANDS (H/BH)   // 32
#define BIGF 3.0e38f
#define PREP_BLOCKS 512

// ---- scratch (device globals; no allocation) ----
// g_skel stores q = 1 - skel  (multiplicative form: q *= (1 - delta))
__device__ float g_imgA[(size_t)NIMG*HW];
__device__ float g_imgB[(size_t)NIMG*HW];
__device__ float g_skel[(size_t)NIMG*HW];
__device__ float g_dicePart[PREP_BLOCKS*3];   // [block][inter,sumT,sumP]
__device__ float g_epPart[NIMG*NBANDS*3];     // [img][band][s,sy,sx]

__device__ __forceinline__ float f3min(float a,float b,float c){return fminf(fminf(a,b),c);}
__device__ __forceinline__ float f3max(float a,float b,float c){return fmaxf(fmaxf(a,b),c);}

// ---------------------------------------------------------------------------
// prep: prob = sigmoid(x1-x0); true->float; dice partials. (vectorized)
// ---------------------------------------------------------------------------
__global__ __launch_bounds__(256) void prep_kernel(const float* __restrict__ net,
                                                   const int* __restrict__ yt) {
    const int b   = blockIdx.x >> 6;          // image 0..7
    const int seg = blockIdx.x & 63;          // segment 0..63
    const int tid = threadIdx.x;
    const float4* x0p = (const float4*)(net + (size_t)b*2*HW);
    const float4* x1p = (const float4*)(net + (size_t)b*2*HW + HW);
    const int4*   ytp = (const int4*)(yt + (size_t)b*HW);
    float4* probp = (float4*)(g_imgA + (size_t)b*HW);
    float4* truep = (float4*)(g_imgA + (size_t)(NB + b)*HW);

    float inter = 0.f, st = 0.f, sp = 0.f;
    #pragma unroll
    for (int j = 0; j < 4; j++) {
        int i = seg*1024 + j*256 + tid;       // float4 index within image
        float4 x0 = x0p[i];
        float4 x1 = x1p[i];
        int4 ti = ytp[i];
        float4 pr;
        pr.x = 1.f / (1.f + __expf(x0.x - x1.x));
        pr.y = 1.f / (1.f + __expf(x0.y - x1.y));
        pr.z = 1.f / (1.f + __expf(x0.z - x1.z));
        pr.w = 1.f / (1.f + __expf(x0.w - x1.w));
        float4 tf = make_float4((float)ti.x, (float)ti.y, (float)ti.z, (float)ti.w);
        probp[i] = pr;
        truep[i] = tf;
        inter += tf.x*pr.x + tf.y*pr.y + tf.z*pr.z + tf.w*pr.w;
        st += tf.x + tf.y + tf.z + tf.w;
        sp += pr.x + pr.y + pr.z + pr.w;
    }
    __shared__ float s[3][256];
    s[0][tid] = inter; s[1][tid] = st; s[2][tid] = sp;
    __syncthreads();
    for (int off = 128; off > 0; off >>= 1) {
        if (tid < off) {
            s[0][tid] += s[0][tid + off];
            s[1][tid] += s[1][tid + off];
            s[2][tid] += s[2][tid + off];
        }
        __syncthreads();
    }
    if (tid == 0) {
        g_dicePart[blockIdx.x*3 + 0] = s[0][0];
        g_dicePart[blockIdx.x*3 + 1] = s[1][0];
        g_dicePart[blockIdx.x*3 + 2] = s[2][0];
    }
}

// ---------------------------------------------------------------------------
// INIT sweep: q = 1 - relu(img - dilate3x3(erode(img))). FULLY UNROLLED.
// ---------------------------------------------------------------------------
__global__ __launch_bounds__(128, 4) void sweep_init_kernel() {
    const int img = blockIdx.y;
    const int R0row = blockIdx.x * BH;
    const int lane = threadIdx.x & 31;
    const int colBase = ((threadIdx.x >> 5) << 7) + (lane << 2);
    const bool isL = (lane == 0), isR = (lane == 31);
    const bool edgeL = (colBase == 0), edgeR = (colBase == W-4);
    const float* __restrict__ in = g_imgA + (size_t)img*HW;
    float* __restrict__ skel = g_skel + (size_t)img*HW;

    const float4 PINF = make_float4(BIGF,BIGF,BIGF,BIGF);
    float4 i0=PINF, i1=PINF, L0=PINF, L1=PINF, Rv0=PINF, Rv1=PINF;
    float4 hp=PINF; float hpL1=BIGF, hpR0=BIGF;
    float4 e1a=make_float4(-BIGF,-BIGF,-BIGF,-BIGF), e1b=e1a;
    float e1aL=-BIGF, e1bL=-BIGF, e1aR=-BIGF, e1bR=-BIGF;

    const int rStart = R0row-2, rEnd = R0row+BH+1;   // BH+4 = 20 rows
    float4 nCur=PINF, nL=PINF, nR=PINF;
    if (rStart >= 0 && rStart < H) {
        const float* p = in + rStart*W + colBase;
        nCur = *(const float4*)p;
        if (isL && !edgeL) nL = *(const float4*)(p - 4);
        if (isR && !edgeR) nR = *(const float4*)(p + 4);
    }

    #pragma unroll
    for (int t = 0; t < BH+4; t++) {
        const int r = rStart + t;
        float4 cur = nCur, Lc = nL, Rc = nR;
        nCur = PINF; nL = PINF; nR = PINF;
        {
            int rn = r + 1;
            if (rn <= rEnd && (unsigned)rn < (unsigned)H) {
                const float* p = in + rn*W + colBase;
                nCur = *(const float4*)p;
                if (isL && !edgeL) nL = *(const float4*)(p - 4);
                if (isR && !edgeR) nR = *(const float4*)(p + 4);
            }
        }
        float xm1 = __shfl_up_sync(0xffffffffu, cur.w, 1); if (isL) xm1 = Lc.w;
        float xp1 = __shfl_down_sync(0xffffffffu, cur.x, 1); if (isR) xp1 = Rc.x;
        float4 hc;
        hc.x = f3min(xm1, cur.x, cur.y);
        hc.y = f3min(cur.x, cur.y, cur.z);
        hc.z = f3min(cur.y, cur.z, cur.w);
        hc.w = f3min(cur.z, cur.w, xp1);
        float hcL1 = f3min(Lc.z, Lc.w, cur.x);
        float hcR0 = f3min(cur.w, Rc.x, Rc.y);

        float4 e1n;
        e1n.x = fminf(f3min(i0.x,i1.x,cur.x), hp.x);
        e1n.y = fminf(f3min(i0.y,i1.y,cur.y), hp.y);
        e1n.z = fminf(f3min(i0.z,i1.z,cur.z), hp.z);
        e1n.w = fminf(f3min(i0.w,i1.w,cur.w), hp.w);
        float e1nL = fminf(f3min(L0.w,L1.w,Lc.w), hpL1);
        float e1nR = fminf(f3min(Rv0.x,Rv1.x,Rc.x), hpR0);
        {
            int k = r-1;
            if (k < 0 || k >= H) {
                e1n = make_float4(-BIGF,-BIGF,-BIGF,-BIGF);
                e1nL = e1nR = -BIGF;
            }
        }
        if (edgeL) e1nL = -BIGF;
        if (edgeR) e1nR = -BIGF;

        if (t >= 4) {   // r >= R0row+2
            float4 mv;
            mv.x = f3max(e1a.x, e1b.x, e1n.x);
            mv.y = f3max(e1a.y, e1b.y, e1n.y);
            mv.z = f3max(e1a.z, e1b.z, e1n.z);
            mv.w = f3max(e1a.w, e1b.w, e1n.w);
            float mvL = f3max(e1aL, e1bL, e1nL);
            float mvR = f3max(e1aR, e1bR, e1nR);
            float mm1 = __shfl_up_sync(0xffffffffu, mv.w, 1); if (isL) mm1 = mvL;
            float mp1 = __shfl_down_sync(0xffffffffu, mv.x, 1); if (isR) mp1 = mvR;
            float4 open;
            open.x = f3max(mm1, mv.x, mv.y);
            open.y = f3max(mv.x, mv.y, mv.z);
            open.z = f3max(mv.y, mv.z, mv.w);
            open.w = f3max(mv.z, mv.w, mp1);
            int k2 = r-2;
            float4 s;
            s.x = 1.f - fmaxf(i0.x - open.x, 0.f);
            s.y = 1.f - fmaxf(i0.y - open.y, 0.f);
            s.z = 1.f - fmaxf(i0.z - open.z, 0.f);
            s.w = 1.f - fmaxf(i0.w - open.w, 0.f);
            *(float4*)(skel + k2*W + colBase) = s;
        }
        i0=i1; i1=cur; L0=L1; L1=Lc; Rv0=Rv1; Rv1=Rc;
        hp=hc; hpL1=hcL1; hpR0=hcR0;
        e1a=e1b; e1b=e1n; e1aL=e1bL; e1bL=e1nL; e1aR=e1bR; e1bR=e1nR;
    }
}

// ---------------------------------------------------------------------------
// STEP body (iterations 0..38), FULLY UNROLLED. Same as R14 winner.
// ---------------------------------------------------------------------------
template<bool BOUNDARY>
__device__ __forceinline__ void step_body(
    const float* __restrict__ in, float* __restrict__ outImg,
    float* __restrict__ skel, int R0row, int colBase,
    bool isL, bool isR, bool edgeL, bool edgeR)
{
    const float4 PINF = make_float4(BIGF,BIGF,BIGF,BIGF);
    const float4 NINF = make_float4(-BIGF,-BIGF,-BIGF,-BIGF);

    float4 i0=PINF, i1=PINF, L0=PINF, L1=PINF, Rv0=PINF, Rv1=PINF;
    float4 hp=PINF; float hpL0=BIGF, hpL1=BIGF, hpR0=BIGF, hpR1=BIGF;
    float4 e1a=PINF, e1b=PINF; float e1aL=BIGF, e1bL=BIGF, e1aR=BIGF, e1bR=BIGF;
    float4 h1p=PINF; float h1pL=BIGF, h1pR=BIGF;
    float4 e2a=NINF, e2b=NINF; float e2aL=-BIGF, e2bL=-BIGF, e2aR=-BIGF, e2bR=-BIGF;

    const int rStart = R0row-3, rEnd = R0row+BH+2;   // BH+6 = 22 rows
    float4 nCur=PINF, nL=PINF, nR=PINF, nSk=make_float4(0,0,0,0);
    if (!BOUNDARY || (rStart >= 0 && rStart < H)) {
        const float* p = in + rStart*W + colBase;
        nCur = *(const float4*)p;
        if (isL && !edgeL) nL = *(const float4*)(p - 4);
        if (isR && !edgeR) nR = *(const float4*)(p + 4);
    }

    #pragma unroll
    for (int t = 0; t < BH+6; t++) {
        const int r = rStart + t;
        float4 cur = nCur, Lc = nL, Rc = nR, skv = nSk;
        {
            int rn = r + 1;
            if (BOUNDARY) {
                nCur = PINF; nL = PINF; nR = PINF;
                if (rn <= rEnd && (unsigned)rn < (unsigned)H) {
                    const float* p = in + rn*W + colBase;
                    nCur = *(const float4*)p;
                    if (isL && !edgeL) nL = *(const float4*)(p - 4);
                    if (isR && !edgeR) nR = *(const float4*)(p + 4);
                }
                if (rn >= R0row+3 && rn <= rEnd)
                    nSk = *(const float4*)(skel + (rn-3)*W + colBase);
            } else {
                const float* p = in + rn*W + colBase;
                nCur = *(const float4*)p;
                nL = PINF; nR = PINF;
                if (isL && !edgeL) nL = *(const float4*)(p - 4);
                if (isR && !edgeR) nR = *(const float4*)(p + 4);
                nSk = *(const float4*)(skel + (rn-3)*W + colBase);
            }
        }
        float xm1 = __shfl_up_sync(0xffffffffu, cur.w, 1); if (isL) xm1 = Lc.w;
        float xp1 = __shfl_down_sync(0xffffffffu, cur.x, 1); if (isR) xp1 = Rc.x;
        float4 hc;
        hc.x = f3min(xm1, cur.x, cur.y);
        hc.y = f3min(cur.x, cur.y, cur.z);
        hc.z = f3min(cur.y, cur.z, cur.w);
        hc.w = f3min(cur.z, cur.w, xp1);
        float hcL0 = f3min(Lc.y, Lc.z, Lc.w);
        float hcL1 = f3min(Lc.z, Lc.w, cur.x);
        float hcR0 = f3min(cur.w, Rc.x, Rc.y);
        float hcR1 = f3min(Rc.x, Rc.y, Rc.z);

        float4 e1n;
        e1n.x = fminf(f3min(i0.x,i1.x,cur.x), hp.x);
        e1n.y = fminf(f3min(i0.y,i1.y,cur.y), hp.y);
        e1n.z = fminf(f3min(i0.z,i1.z,cur.z), hp.z);
        e1n.w = fminf(f3min(i0.w,i1.w,cur.w), hp.w);
        float e1nL0 = fminf(f3min(L0.z,L1.z,Lc.z), hpL0);
        float e1nL1 = fminf(f3min(L0.w,L1.w,Lc.w), hpL1);
        float e1nR0 = fminf(f3min(Rv0.x,Rv1.x,Rc.x), hpR0);
        float e1nR1 = fminf(f3min(Rv0.y,Rv1.y,Rc.y), hpR1);
        if (BOUNDARY) {
            int k = r-1;
            if (k < 0 || k >= H) { e1n = PINF; e1nL0=e1nL1=e1nR0=e1nR1=BIGF; }
        }
        float em1 = __shfl_up_sync(0xffffffffu, e1n.w, 1); if (isL) em1 = e1nL1;
        float ep1 = __shfl_down_sync(0xffffffffu, e1n.x, 1); if (isR) ep1 = e1nR0;
        float4 h1c;
        h1c.x = f3min(em1, e1n.x, e1n.y);
        h1c.y = f3min(e1n.x, e1n.y, e1n.z);
        h1c.z = f3min(e1n.y, e1n.z, e1n.w);
        h1c.w = f3min(e1n.z, e1n.w, ep1);
        float h1cL = f3min(e1nL0, e1nL1, e1n.x);
        float h1cR = f3min(e1n.w, e1nR0, e1nR1);

        float4 e2n;
        e2n.x = fminf(f3min(e1a.x,e1b.x,e1n.x), h1p.x);
        e2n.y = fminf(f3min(e1a.y,e1b.y,e1n.y), h1p.y);
        e2n.z = fminf(f3min(e1a.z,e1b.z,e1n.z), h1p.z);
        e2n.w = fminf(f3min(e1a.w,e1b.w,e1n.w), h1p.w);
        float e2nL = fminf(f3min(e1aL,e1bL,e1nL1), h1pL);
        float e2nR = fminf(f3min(e1aR,e1bR,e1nR0), h1pR);
        if (BOUNDARY) {
            int j = r-2;
            if (j < 0 || j >= H) { e2n = NINF; e2nL = e2nR = -BIGF; }
        }
        if (edgeL) e2nL = -BIGF;
        if (edgeR) e2nR = -BIGF;

        if (t >= 6) {
            float4 mv;
            mv.x = f3max(e2a.x, e2b.x, e2n.x);
            mv.y = f3max(e2a.y, e2b.y, e2n.y);
            mv.z = f3max(e2a.z, e2b.z, e2n.z);
            mv.w = f3max(e2a.w, e2b.w, e2n.w);
            float mvL = f3max(e2aL, e2bL, e2nL);
            float mvR = f3max(e2aR, e2bR, e2nR);
            float mm1 = __shfl_up_sync(0xffffffffu, mv.w, 1); if (isL) mm1 = mvL;
            float mp1 = __shfl_down_sync(0xffffffffu, mv.x, 1); if (isR) mp1 = mvR;
            float4 open;
            open.x = f3max(mm1, mv.x, mv.y);
            open.y = f3max(mv.x, mv.y, mv.z);
            open.z = f3max(mv.y, mv.z, mv.w);
            open.w = f3max(mv.z, mv.w, mp1);
            int k2 = r-3;
            float4 ec = e1a;
            float4 q = skv;
            float d0 = fmaxf(ec.x - open.x, 0.f); q.x -= q.x*d0;
            float d1 = fmaxf(ec.y - open.y, 0.f); q.y -= q.y*d1;
            float d2 = fmaxf(ec.z - open.z, 0.f); q.z -= q.z*d2;
            float d3 = fmaxf(ec.w - open.w, 0.f); q.w -= q.w*d3;
            *(float4*)(skel + k2*W + colBase) = q;
            *(float4*)(outImg + k2*W + colBase) = ec;
        }
        i0=i1; i1=cur; L0=L1; L1=Lc; Rv0=Rv1; Rv1=Rc;
        hp=hc; hpL0=hcL0; hpL1=hcL1; hpR0=hcR0; hpR1=hcR1;
        e1a=e1b; e1b=e1n; e1aL=e1bL; e1bL=e1nL1; e1aR=e1bR; e1bR=e1nR0;
        h1p=h1c; h1pL=h1cL; h1pR=h1cR;
        e2a=e2b; e2b=e2n; e2aL=e2bL; e2bL=e2nL; e2aR=e2bR; e2bR=e2nR;
    }
}

__global__ __launch_bounds__(128, 4) void sweep_step_kernel(int bufsel) {
    const int img = blockIdx.y;
    const int band = blockIdx.x;
    const int R0row = band * BH;
    const int lane = threadIdx.x & 31;
    const int colBase = ((threadIdx.x >> 5) << 7) + (lane << 2);
    const bool isL = (lane == 0), isR = (lane == 31);
    const bool edgeL = (colBase == 0), edgeR = (colBase == W-4);
    const float* __restrict__ in     = (bufsel ? g_imgB : g_imgA) + (size_t)img*HW;
    float*       __restrict__ outImg = (bufsel ? g_imgA : g_imgB) + (size_t)img*HW;
    float*       __restrict__ skel   = g_skel + (size_t)img*HW;

    if (band == 0 || band == NBANDS-1)
        step_body<true >(in, outImg, skel, R0row, colBase, isL, isR, edgeL, edgeR);
    else
        step_body<false>(in, outImg, skel, R0row, colBase, isL, isR, edgeL, edgeR);
}

// ---------------------------------------------------------------------------
// FINAL fused kernel: last morphology iteration + endpoint conv + partials.
// Extended sweep: rStart = R0row-4, 24 rows, outputs skel rows
// k2 in [R0row-1, R0row+BH] (18 rows) -> smem (no global skel/img writes).
// The two extra rows recompute neighbors' deltas bit-identically.
// Then 3x3 endpoint conv + per-band partial sums, all from smem.
// ---------------------------------------------------------------------------
#define SROWS 18
#define SPITCH 516
template<bool BOUNDARY>
__device__ __forceinline__ void final_body(
    const float* __restrict__ in, const float* __restrict__ skel,
    int R0row, int colBase,
    bool isL, bool isR, bool edgeL, bool edgeR,
    float (*sk_s)[SPITCH])
{
    const float4 PINF = make_float4(BIGF,BIGF,BIGF,BIGF);
    const float4 NINF = make_float4(-BIGF,-BIGF,-BIGF,-BIGF);

    float4 i0=PINF, i1=PINF, L0=PINF, L1=PINF, Rv0=PINF, Rv1=PINF;
    float4 hp=PINF; float hpL0=BIGF, hpL1=BIGF, hpR0=BIGF, hpR1=BIGF;
    float4 e1a=PINF, e1b=PINF; float e1aL=BIGF, e1bL=BIGF, e1aR=BIGF, e1bR=BIGF;
    float4 h1p=PINF; float h1pL=BIGF, h1pR=BIGF;
    float4 e2a=NINF, e2b=NINF; float e2aL=-BIGF, e2bL=-BIGF, e2aR=-BIGF, e2bR=-BIGF;

    const int rStart = R0row-4;               // 24 rows: t = 0..BH+7
    float4 nCur=PINF, nL=PINF, nR=PINF, nSk=make_float4(0,0,0,0);
    if (!BOUNDARY || ((unsigned)rStart < (unsigned)H)) {
        const float* p = in + rStart*W + colBase;
        nCur = *(const float4*)p;
        if (isL && !edgeL) nL = *(const float4*)(p - 4);
        if (isR && !edgeR) nR = *(const float4*)(p + 4);
    }

    #pragma unroll
    for (int t = 0; t < BH+8; t++) {
        const int r = rStart + t;
        float4 cur = nCur, Lc = nL, Rc = nR, skv = nSk;
        {
            int rn = r + 1;   // prefetch img row rn and q row rn-3
            if (BOUNDARY) {
                nCur = PINF; nL = PINF; nR = PINF;
                if ((unsigned)rn < (unsigned)H && t+1 <= BH+7) {
                    const float* p = in + rn*W + colBase;
                    nCur = *(const float4*)p;
                    if (isL && !edgeL) nL = *(const float4*)(p - 4);
                    if (isR && !edgeR) nR = *(const float4*)(p + 4);
                }
                nSk = make_float4(0,0,0,0);
                if (t+1 >= 6 && t+1 <= BH+7 && (unsigned)(rn-3) < (unsigned)H)
                    nSk = *(const float4*)(skel + (rn-3)*W + colBase);
            } else {
                if (t+1 <= BH+7) {
                    const float* p = in + rn*W + colBase;
                    nCur = *(const float4*)p;
                    nL = PINF; nR = PINF;
                    if (isL && !edgeL) nL = *(const float4*)(p - 4);
                    if (isR && !edgeR) nR = *(const float4*)(p + 4);
                }
                if (t+1 >= 6 && t+1 <= BH+7)
                    nSk = *(const float4*)(skel + (rn-3)*W + colBase);
            }
        }
        float xm1 = __shfl_up_sync(0xffffffffu, cur.w, 1); if (isL) xm1 = Lc.w;
        float xp1 = __shfl_down_sync(0xffffffffu, cur.x, 1); if (isR) xp1 = Rc.x;
        float4 hc;
        hc.x = f3min(xm1, cur.x, cur.y);
        hc.y = f3min(cur.x, cur.y, cur.z);
        hc.z = f3min(cur.y, cur.z, cur.w);
        hc.w = f3min(cur.z, cur.w, xp1);
        float hcL0 = f3min(Lc.y, Lc.z, Lc.w);
        float hcL1 = f3min(Lc.z, Lc.w, cur.x);
        float hcR0 = f3min(cur.w, Rc.x, Rc.y);
        float hcR1 = f3min(Rc.x, Rc.y, Rc.z);

        float4 e1n;
        e1n.x = fminf(f3min(i0.x,i1.x,cur.x), hp.x);
        e1n.y = fminf(f3min(i0.y,i1.y,cur.y), hp.y);
        e1n.z = fminf(f3min(i0.z,i1.z,cur.z), hp.z);
        e1n.w = fminf(f3min(i0.w,i1.w,cur.w), hp.w);
        float e1nL0 = fminf(f3min(L0.z,L1.z,Lc.z), hpL0);
        float e1nL1 = fminf(f3min(L0.w,L1.w,Lc.w), hpL1);
        float e1nR0 = fminf(f3min(Rv0.x,Rv1.x,Rc.x), hpR0);
        float e1nR1 = fminf(f3min(Rv0.y,Rv1.y,Rc.y), hpR1);
        if (BOUNDARY) {
            int k = r-1;
            if (k < 0 || k >= H) { e1n = PINF; e1nL0=e1nL1=e1nR0=e1nR1=BIGF; }
        }
        float em1 = __shfl_up_sync(0xffffffffu, e1n.w, 1); if (isL) em1 = e1nL1;
        float ep1 = __shfl_down_sync(0xffffffffu, e1n.x, 1); if (isR) ep1 = e1nR0;
        float4 h1c;
        h1c.x = f3min(em1, e1n.x, e1n.y);
        h1c.y = f3min(e1n.x, e1n.y, e1n.z);
        h1c.z = f3min(e1n.y, e1n.z, e1n.w);
        h1c.w = f3min(e1n.z, e1n.w, ep1);
        float h1cL = f3min(e1nL0, e1nL1, e1n.x);
        float h1cR = f3min(e1n.w, e1nR0, e1nR1);

        float4 e2n;
        e2n.x = fminf(f3min(e1a.x,e1b.x,e1n.x), h1p.x);
        e2n.y = fminf(f3min(e1a.y,e1b.y,e1n.y), h1p.y);
        e2n.z = fminf(f3min(e1a.z,e1b.z,e1n.z), h1p.z);
        e2n.w = fminf(f3min(e1a.w,e1b.w,e1n.w), h1p.w);
        float e2nL = fminf(f3min(e1aL,e1bL,e1nL1), h1pL);
        float e2nR = fminf(f3min(e1aR,e1bR,e1nR0), h1pR);
        if (BOUNDARY) {
            int j = r-2;
            if (j < 0 || j >= H) { e2n = NINF; e2nL = e2nR = -BIGF; }
        }
        if (edgeL) e2nL = -BIGF;
        if (edgeR) e2nR = -BIGF;

        if (t >= 6) {   // out row k2 = r-3 in [R0row-1, R0row+BH]; smem row t-6
            const int k2 = r-3;
            const int srow = t-6;
            float4 sv = make_float4(0,0,0,0);   // zero-pad for invalid rows
            if (!BOUNDARY || ((unsigned)k2 < (unsigned)H)) {
                float4 mv;
                mv.x = f3max(e2a.x, e2b.x, e2n.x);
                mv.y = f3max(e2a.y, e2b.y, e2n.y);
                mv.z = f3max(e2a.z, e2b.z, e2n.z);
                mv.w = f3max(e2a.w, e2b.w, e2n.w);
                float mvL = f3max(e2aL, e2bL, e2nL);
                float mvR = f3max(e2aR, e2bR, e2nR);
                float mm1 = __shfl_up_sync(0xffffffffu, mv.w, 1); if (isL) mm1 = mvL;
                float mp1 = __shfl_down_sync(0xffffffffu, mv.x, 1); if (isR) mp1 = mvR;
                float4 open;
                open.x = f3max(mm1, mv.x, mv.y);
                open.y = f3max(mv.x, mv.y, mv.z);
                open.z = f3max(mv.y, mv.z, mv.w);
                open.w = f3max(mv.z, mv.w, mp1);
                float4 ec = e1a;
                float4 q = skv;
                float d0 = fmaxf(ec.x - open.x, 0.f); q.x -= q.x*d0;
                float d1 = fmaxf(ec.y - open.y, 0.f); q.y -= q.y*d1;
                float d2 = fmaxf(ec.z - open.z, 0.f); q.z -= q.z*d2;
                float d3 = fmaxf(ec.w - open.w, 0.f); q.w -= q.w*d3;
                sv = make_float4(1.f-q.x, 1.f-q.y, 1.f-q.z, 1.f-q.w);
            } else {
                // keep warp-uniform shfl execution even when row invalid
                float4 mv;
                mv.x = f3max(e2a.x, e2b.x, e2n.x);
                mv.w = f3max(e2a.w, e2b.w, e2n.w);
                (void)__shfl_up_sync(0xffffffffu, mv.w, 1);
                (void)__shfl_down_sync(0xffffffffu, mv.x, 1);
            }
            *(float4*)&sk_s[srow][colBase] = sv;
        }
        i0=i1; i1=cur; L0=L1; L1=Lc; Rv0=Rv1; Rv1=Rc;
        hp=hc; hpL0=hcL0; hpL1=hcL1; hpR0=hcR0; hpR1=hcR1;
        e1a=e1b; e1b=e1n; e1aL=e1bL; e1bL=e1nL1; e1aR=e1bR; e1bR=e1nR0;
        h1p=h1c; h1pL=h1cL; h1pR=h1cR;
        e2a=e2b; e2b=e2n; e2aL=e2bL; e2bL=e2nL; e2aR=e2bR; e2bR=e2nR;
    }
}

__global__ __launch_bounds__(128, 4) void final_step_kernel(int bufsel) {
    const int img = blockIdx.y;
    const int band = blockIdx.x;
    const int R0row = band * BH;
    const int lane = threadIdx.x & 31;
    const int colBase = ((threadIdx.x >> 5) << 7) + (lane << 2);
    const bool isL = (lane == 0), isR = (lane == 31);
    const bool edgeL = (colBase == 0), edgeR = (colBase == W-4);
    const float* __restrict__ in   = (bufsel ? g_imgB : g_imgA) + (size_t)img*HW;
    const float* __restrict__ skel = g_skel + (size_t)img*HW;

    __shared__ float sk_s[SROWS][SPITCH];

    if (band == 0 || band == NBANDS-1)
        final_body<true >(in, skel, R0row, colBase, isL, isR, edgeL, edgeR, sk_s);
    else
        final_body<false>(in, skel, R0row, colBase, isL, isR, edgeL, edgeR, sk_s);

    __syncthreads();

    // endpoint conv from smem: band rows kk=0..BH-1 (global row R0row+kk),
    // center = smem row kk+1; vertical window rows kk..kk+2.
    float r0c[6], r1c[6], r2c[6];
    #pragma unroll
    for (int j = 0; j < 6; j++) { r0c[j] = 0.f; r1c[j] = 0.f; }
    {   // load smem rows 0 and 1 (cols colBase-1 .. colBase+4, zero-pad edges)
        #pragma unroll
        for (int s = 0; s < 2; s++) {
            float* dst = s ? r1c : r0c;
            const float* row = sk_s[s];
            dst[0] = edgeL ? 0.f : row[colBase-1];
            float4 v = *(const float4*)&row[colBase];
            dst[1]=v.x; dst[2]=v.y; dst[3]=v.z; dst[4]=v.w;
            dst[5] = edgeR ? 0.f : row[colBase+4];
        }
    }
    float s0 = 0.f, sy = 0.f, sx = 0.f;
    #pragma unroll
    for (int kk = 0; kk < BH; kk++) {
        const float* row = sk_s[kk+2];
        r2c[0] = edgeL ? 0.f : row[colBase-1];
        float4 v = *(const float4*)&row[colBase];
        r2c[1]=v.x; r2c[2]=v.y; r2c[3]=v.z; r2c[4]=v.w;
        r2c[5] = edgeR ? 0.f : row[colBase+4];

        float vs0 = r0c[0]+r1c[0]+r2c[0];
        float vs1 = r0c[1]+r1c[1]+r2c[1];
        float vs2 = r0c[2]+r1c[2]+r2c[2];
        float vs3 = r0c[3]+r1c[3]+r2c[3];
        float vs4 = r0c[4]+r1c[4]+r2c[4];
        float vs5 = r0c[5]+r1c[5]+r2c[5];
        float c0 = r1c[1], c1 = r1c[2], c2 = r1c[3], c3 = r1c[4];
        float ns0 = vs0+vs1+vs2 + 9.f*c0;
        float ns1 = vs1+vs2+vs3 + 9.f*c1;
        float ns2 = vs2+vs3+vs4 + 9.f*c2;
        float ns3 = vs3+vs4+vs5 + 9.f*c3;
        float d0 = ns0-11.f, d1 = ns1-11.f, d2 = ns2-11.f, d3 = ns3-11.f;
        float e0 = __expf(-d0*d0)*c0;
        float e1 = __expf(-d1*d1)*c1;
        float e2 = __expf(-d2*d2)*c2;
        float e3 = __expf(-d3*d3)*c3;
        float es = e0+e1+e2+e3;
        s0 += es;
        sy += es * (float)(R0row + kk);
        sx += e0*(float)colBase + e1*(float)(colBase+1)
            + e2*(float)(colBase+2) + e3*(float)(colBase+3);
        #pragma unroll
        for (int j = 0; j < 6; j++) { r0c[j] = r1c[j]; r1c[j] = r2c[j]; }
    }

    __syncthreads();   // reuse of smem below
    __shared__ float s[3][128];
    s[0][threadIdx.x] = s0; s[1][threadIdx.x] = sy; s[2][threadIdx.x] = sx;
    __syncthreads();
    for (int off = 64; off > 0; off >>= 1) {
        if (threadIdx.x < off) {
            s[0][threadIdx.x] += s[0][threadIdx.x + off];
            s[1][threadIdx.x] += s[1][threadIdx.x + off];
            s[2][threadIdx.x] += s[2][threadIdx.x + off];
        }
        __syncthreads();
    }
    if (threadIdx.x == 0) {
        int o = (img*NBANDS + band)*3;
        g_epPart[o + 0] = s[0][0];
        g_epPart[o + 1] = s[1][0];
        g_epPart[o + 2] = s[2][0];
    }
}

// ---------------------------------------------------------------------------
// final: combine everything into the scalar loss. (512 dice partials)
// ---------------------------------------------------------------------------
__global__ __launch_bounds__(256) void final_kernel(float* __restrict__ out) {
    __shared__ float s[3][256];
    {
        int i0 = threadIdx.x, i1 = threadIdx.x + 256;
        s[0][threadIdx.x] = g_dicePart[i0*3 + 0] + g_dicePart[i1*3 + 0];
        s[1][threadIdx.x] = g_dicePart[i0*3 + 1] + g_dicePart[i1*3 + 1];
        s[2][threadIdx.x] = g_dicePart[i0*3 + 2] + g_dicePart[i1*3 + 2];
    }
    __syncthreads();
    for (int off = 128; off > 0; off >>= 1) {
        if (threadIdx.x < off) {
            s[0][threadIdx.x] += s[0][threadIdx.x + off];
            s[1][threadIdx.x] += s[1][threadIdx.x + off];
            s[2][threadIdx.x] += s[2][threadIdx.x + off];
        }
        __syncthreads();
    }
    __shared__ float S[NIMG], SY[NIMG], SX[NIMG];
    if (threadIdx.x < NIMG) {
        float t0 = 0.f, t1 = 0.f, t2 = 0.f;
        for (int bd = 0; bd < NBANDS; bd++) {
            int o = (threadIdx.x*NBANDS + bd)*3;
            t0 += g_epPart[o + 0];
            t1 += g_epPart[o + 1];
            t2 += g_epPart[o + 2];
        }
        S[threadIdx.x] = t0; SY[threadIdx.x] = t1; SX[threadIdx.x] = t2;
    }
    __syncthreads();
    if (threadIdx.x == 0) {
        float inter = s[0][0], sumT = s[1][0], sumP = s[2][0];
        float dice = 1.f - (2.f*inter + 1.f) / (sumT + sumP + 1.f);
        float distsum = 0.f, cntsum = 0.f;
        for (int b = 0; b < NB; b++) {
            float np = S[b], nt = S[NB + b];
            float tp = np + 1e-8f, tt = nt + 1e-8f;
            float ycp = SY[b] / tp,      xcp = SX[b] / tp;
            float yct = SY[NB+b] / tt,   xct = SX[NB+b] / tt;
            float dy = ycp - yct, dx = xcp - xct;
            distsum += sqrtf(dy*dy + dx*dx);
            cntsum  += fabsf(np - nt) / (np + nt + 1e-8f);
        }
        float diag = sqrtf((float)(H*H) + (float)(W*W));
        float distance_loss = (distsum / (float)NB) / (diag * 1.0f + 1e-8f);
        float count_penalty = cntsum / (float)NB;
        out[0] = 0.85f * dice + 0.15f * (distance_loss + count_penalty);
    }
}

// ---------------------------------------------------------------------------
extern "C" void kernel_launch(void* const* d_in, const int* in_sizes, int n_in,
                              void* d_out, int out_size) {
    const float* net = (const float*)d_in[0];
    const int*   yt  = (const int*)d_in[1];
    float* out = (float*)d_out;
    (void)in_sizes; (void)n_in; (void)out_size;

    prep_kernel<<<PREP_BLOCKS, 256>>>(net, yt);

    dim3 grid(NBANDS, NIMG);
    sweep_init_kernel<<<grid, 128>>>();             // q init; img stays in A
    for (int i = 0; i < NUM_ITER-1; i++)            // iterations 0..38
        sweep_step_kernel<<<grid, 128>>>(i & 1);
    final_step_kernel<<<grid, 128>>>((NUM_ITER-1) & 1);  // iter 39 + endpoint
    final_kernel<<<1, 256>>>(out);
}